// round 1
// baseline (speedup 1.0000x reference)
#include <cuda_runtime.h>
#include <cstdint>

#define T_STEPS 512
#define B_SZ    64
#define NIN     256
#define NHID    1024
#define NOUT    256
#define MROWS   (T_STEPS * B_SZ)   // 32768

// 128 MB scratch for the relu'd input projection X = relu(IN @ W_in^T + b_in)
__device__ float g_X[(size_t)MROWS * NHID];

// ---------------------------------------------------------------------------
// Generic fp32 GEMM:  C[M,N] = act( A[M,K] @ Bw[N,K]^T + bias1 (+ bias2) )
// Both operands are K-contiguous (row-major A, row-major weight [N,K]).
// 128x128 block tile, BK=8, 256 threads, 8x8 register micro-tile.
// Requires M%128==0, N%128==0, K%8==0 (true for all phases here).
// ---------------------------------------------------------------------------
template <bool RELU, bool TWO_BIAS>
__global__ void __launch_bounds__(256)
sgemm_nt(const float* __restrict__ A, const float* __restrict__ Bw,
         const float* __restrict__ bias1, const float* __restrict__ bias2,
         float* __restrict__ C, int M, int N, int K)
{
    const int BM = 128, BN = 128, BK = 8;
    __shared__ float As[BK][BM + 4];
    __shared__ float Bs[BK][BN + 4];

    const int bm  = blockIdx.y * BM;
    const int bn  = blockIdx.x * BN;
    const int tid = threadIdx.x;

    // global loader mapping: 256 threads load 128 rows x 8 k as float4
    const int lrow  = tid >> 1;          // 0..127
    const int lk4   = (tid & 1) * 4;     // 0 or 4
    const float* Aptr = A  + (size_t)(bm + lrow) * K + lk4;
    const float* Bptr = Bw + (size_t)(bn + lrow) * K + lk4;

    // compute mapping: 16x16 thread grid, 8x8 micro-tile
    const int tr = (tid >> 4) * 8;       // 0..120
    const int tc = (tid & 15) * 8;       // 0..120

    float acc[8][8];
#pragma unroll
    for (int i = 0; i < 8; ++i)
#pragma unroll
        for (int j = 0; j < 8; ++j) acc[i][j] = 0.f;

    for (int k0 = 0; k0 < K; k0 += BK) {
        float4 av = *(const float4*)(Aptr + k0);
        float4 bv = *(const float4*)(Bptr + k0);
        As[lk4 + 0][lrow] = av.x; As[lk4 + 1][lrow] = av.y;
        As[lk4 + 2][lrow] = av.z; As[lk4 + 3][lrow] = av.w;
        Bs[lk4 + 0][lrow] = bv.x; Bs[lk4 + 1][lrow] = bv.y;
        Bs[lk4 + 2][lrow] = bv.z; Bs[lk4 + 3][lrow] = bv.w;
        __syncthreads();

#pragma unroll
        for (int k = 0; k < BK; ++k) {
            float ra[8], rb[8];
            *(float4*)(ra)     = *(const float4*)(&As[k][tr]);
            *(float4*)(ra + 4) = *(const float4*)(&As[k][tr + 4]);
            *(float4*)(rb)     = *(const float4*)(&Bs[k][tc]);
            *(float4*)(rb + 4) = *(const float4*)(&Bs[k][tc + 4]);
#pragma unroll
            for (int i = 0; i < 8; ++i)
#pragma unroll
                for (int j = 0; j < 8; ++j)
                    acc[i][j] = fmaf(ra[i], rb[j], acc[i][j]);
        }
        __syncthreads();
    }

    // epilogue: bias (+bias2) (+relu), vectorized stores
    float bb[8];
#pragma unroll
    for (int j = 0; j < 8; ++j) {
        float b = bias1[bn + tc + j];
        if (TWO_BIAS) b += bias2[bn + tc + j];
        bb[j] = b;
    }
#pragma unroll
    for (int i = 0; i < 8; ++i) {
        float* cp = C + (size_t)(bm + tr + i) * N + bn + tc;
        float v[8];
#pragma unroll
        for (int j = 0; j < 8; ++j) {
            float x = acc[i][j] + bb[j];
            v[j] = RELU ? fmaxf(x, 0.f) : x;
        }
        *(float4*)(cp)     = *(float4*)(v);
        *(float4*)(cp + 4) = *(float4*)(v + 4);
    }
}

// ---------------------------------------------------------------------------
// One recurrence step:  S[t] += relu(S[t-1]) @ W_hh^T
// S layout: [B_SZ, NHID] per step. Grid = (NHID/128 n-tiles, NHID/64 k-slices)
// = (8, 16) = 128 blocks. Each block: 64x128 output tile over a 64-wide K
// slice, accumulated in registers, combined across k-slices via atomicAdd.
// relu is applied when reading S[t-1] (S stores pre-activation values).
// ---------------------------------------------------------------------------
__global__ void __launch_bounds__(256)
rnn_step(const float* __restrict__ Sprev, float* __restrict__ Scur,
         const float* __restrict__ Whh)
{
    const int BN = 128, KC = 64, BK = 16;
    __shared__ float Hs[BK][B_SZ + 4];   // [k][m], relu'd
    __shared__ float Ws[BK][BN + 4];     // [k][n]

    const int nbase = blockIdx.x * BN;
    const int kbase = blockIdx.y * KC;
    const int tid   = threadIdx.x;

    const int r0 = (tid >> 5) * 8;   // 8 row-groups of 8 rows
    const int c0 = (tid & 31) * 4;   // 32 col-groups of 4 cols

    float acc[8][4];
#pragma unroll
    for (int i = 0; i < 8; ++i)
#pragma unroll
        for (int j = 0; j < 4; ++j) acc[i][j] = 0.f;

    for (int kc = 0; kc < KC; kc += BK) {
        // load H tile: 64 rows x 16 k  (256 float4 / 256 threads)
        {
            int row = tid >> 2;
            int k4  = (tid & 3) * 4;
            float4 v = *(const float4*)(Sprev + (size_t)row * NHID + kbase + kc + k4);
            Hs[k4 + 0][row] = fmaxf(v.x, 0.f);
            Hs[k4 + 1][row] = fmaxf(v.y, 0.f);
            Hs[k4 + 2][row] = fmaxf(v.z, 0.f);
            Hs[k4 + 3][row] = fmaxf(v.w, 0.f);
        }
        // load W tile: 128 rows x 16 k  (512 float4 / 256 threads -> 2 each)
#pragma unroll
        for (int i = 0; i < 2; ++i) {
            int id   = tid + i * 256;
            int nrow = id >> 2;
            int k4   = (id & 3) * 4;
            float4 v = *(const float4*)(Whh + (size_t)(nbase + nrow) * NHID + kbase + kc + k4);
            Ws[k4 + 0][nrow] = v.x; Ws[k4 + 1][nrow] = v.y;
            Ws[k4 + 2][nrow] = v.z; Ws[k4 + 3][nrow] = v.w;
        }
        __syncthreads();

#pragma unroll
        for (int k = 0; k < BK; ++k) {
            float rh[8], rw[4];
            *(float4*)(rh)     = *(const float4*)(&Hs[k][r0]);
            *(float4*)(rh + 4) = *(const float4*)(&Hs[k][r0 + 4]);
            *(float4*)(rw)     = *(const float4*)(&Ws[k][c0]);
#pragma unroll
            for (int i = 0; i < 8; ++i)
#pragma unroll
                for (int j = 0; j < 4; ++j)
                    acc[i][j] = fmaf(rh[i], rw[j], acc[i][j]);
        }
        __syncthreads();
    }

    // combine k-slice partials into S[t]
#pragma unroll
    for (int i = 0; i < 8; ++i) {
        float* dst = Scur + (size_t)(r0 + i) * NHID + nbase + c0;
#pragma unroll
        for (int j = 0; j < 4; ++j)
            atomicAdd(dst + j, acc[i][j]);
    }
}

// ---------------------------------------------------------------------------
// In-place relu over the hiddens region (converts stored pre-activations S
// into the actual hidden states h = relu(S)).
// ---------------------------------------------------------------------------
__global__ void relu_ip(float* __restrict__ p, int n4)
{
    int stride = gridDim.x * blockDim.x;
    for (int i = blockIdx.x * blockDim.x + threadIdx.x; i < n4; i += stride) {
        float4 v = ((float4*)p)[i];
        v.x = fmaxf(v.x, 0.f);
        v.y = fmaxf(v.y, 0.f);
        v.z = fmaxf(v.z, 0.f);
        v.w = fmaxf(v.w, 0.f);
        ((float4*)p)[i] = v;
    }
}

// ---------------------------------------------------------------------------
// Launch: A (input proj) -> B (W_ih proj, writes U_t into hiddens buffer) ->
// 511 sequential recurrence steps -> relu fixup -> D (output proj).
// ---------------------------------------------------------------------------
extern "C" void kernel_launch(void* const* d_in, const int* in_sizes, int n_in,
                              void* d_out, int out_size)
{
    const float* input = (const float*)d_in[0];
    // d_in[1] = length (fixed at 512)
    const float* W_in  = (const float*)d_in[2];
    const float* b_in  = (const float*)d_in[3];
    const float* W_ih  = (const float*)d_in[4];
    const float* b_ih  = (const float*)d_in[5];
    const float* W_hh  = (const float*)d_in[6];
    const float* b_hh  = (const float*)d_in[7];
    const float* W_out = (const float*)d_in[8];
    const float* b_out = (const float*)d_in[9];

    float* hid  = (float*)d_out;                       // [T*B, NHID]
    float* outp = hid + (size_t)MROWS * NHID;          // [T*B, NOUT]

    float* Xp = nullptr;
    cudaGetSymbolAddress((void**)&Xp, g_X);

    dim3 blk(256);

    // Phase A: X = relu(IN @ W_in^T + b_in)      [32768 x 1024], K=256
    sgemm_nt<true, false><<<dim3(NHID / 128, MROWS / 128), blk>>>(
        input, W_in, b_in, nullptr, Xp, MROWS, NHID, NIN);

    // Phase B: S = X @ W_ih^T + b_ih + b_hh      [32768 x 1024], K=1024
    //          written directly into the hiddens region (per-step U_t).
    sgemm_nt<false, true><<<dim3(NHID / 128, MROWS / 128), blk>>>(
        Xp, W_ih, b_ih, b_hh, hid, MROWS, NHID, NHID);

    // Phase C: sequential recurrence. S[0] = U_0 already complete (h0 = 0).
    for (int t = 1; t < T_STEPS; ++t) {
        rnn_step<<<dim3(NHID / 128, NHID / 64), blk>>>(
            hid + (size_t)(t - 1) * B_SZ * NHID,
            hid + (size_t)t * B_SZ * NHID,
            W_hh);
    }

    // Relu fixup: hiddens = relu(S)
    relu_ip<<<8192, 256>>>(hid, (int)((size_t)MROWS * NHID / 4));

    // Phase D: outputs = H @ W_out^T + b_out     [32768 x 256], K=1024
    sgemm_nt<false, false><<<dim3(NOUT / 128, MROWS / 128), blk>>>(
        hid, W_out, b_out, nullptr, outp, MROWS, NOUT, NHID);
}

// round 3
// speedup vs baseline: 1.2789x; 1.2789x over previous
#include <cuda_runtime.h>
#include <cstdint>

#define T_STEPS 512
#define B_SZ    64
#define NIN     256
#define NHID    1024
#define NOUT    256
#define MROWS   (T_STEPS * B_SZ)   // 32768

#define NTILE   16                 // n-tiles of 64 cols
#define KSLICE  8                  // k-slices of 128 k
#define GRID_P  (NTILE * KSLICE)   // 128 persistent blocks
#define NSTEPS  511                // sequential recurrence steps

#define WS_STRIDE 66               // floats per Ws row (8B-aligned float2 reads)
#define HS_STRIDE 68               // floats per Hs row (16B-aligned u64x2 reads)
#define SMEM_BYTES ((128 * WS_STRIDE + 128 * HS_STRIDE) * 4)   // 68608

// 128 MB scratch for X = relu(IN @ W_in^T + b_in)
__device__ float g_X[(size_t)MROWS * NHID];

// persistent-kernel synchronization state (monotonic, never reset)
__device__ unsigned long long g_epoch;
__device__ unsigned long long g_bar;

__global__ void epoch_bump() { g_epoch += 1ULL; }

// packed fp32x2 FMA (Blackwell): acc = a*b + acc, lane-wise on 2 floats
#define FMA2(acc, a, b) \
    asm volatile("fma.rn.f32x2 %0, %1, %2, %0;" : "+l"(acc) : "l"(a), "l"(b))

// ---------------------------------------------------------------------------
// Generic fp32 GEMM:  C[M,N] = act( A[M,K] @ Bw[N,K]^T + bias1 (+ bias2) )
// 128x128 block tile, BK=8, 256 threads, 8x8 micro-tile.
// ---------------------------------------------------------------------------
template <bool RELU, bool TWO_BIAS>
__global__ void __launch_bounds__(256)
sgemm_nt(const float* __restrict__ A, const float* __restrict__ Bw,
         const float* __restrict__ bias1, const float* __restrict__ bias2,
         float* __restrict__ C, int M, int N, int K)
{
    const int BM = 128, BN = 128, BK = 8;
    __shared__ float As[BK][BM + 4];
    __shared__ float Bs[BK][BN + 4];

    const int bm  = blockIdx.y * BM;
    const int bn  = blockIdx.x * BN;
    const int tid = threadIdx.x;

    const int lrow  = tid >> 1;
    const int lk4   = (tid & 1) * 4;
    const float* Aptr = A  + (size_t)(bm + lrow) * K + lk4;
    const float* Bptr = Bw + (size_t)(bn + lrow) * K + lk4;

    const int tr = (tid >> 4) * 8;
    const int tc = (tid & 15) * 8;

    float acc[8][8];
#pragma unroll
    for (int i = 0; i < 8; ++i)
#pragma unroll
        for (int j = 0; j < 8; ++j) acc[i][j] = 0.f;

    for (int k0 = 0; k0 < K; k0 += BK) {
        float4 av = *(const float4*)(Aptr + k0);
        float4 bv = *(const float4*)(Bptr + k0);
        As[lk4 + 0][lrow] = av.x; As[lk4 + 1][lrow] = av.y;
        As[lk4 + 2][lrow] = av.z; As[lk4 + 3][lrow] = av.w;
        Bs[lk4 + 0][lrow] = bv.x; Bs[lk4 + 1][lrow] = bv.y;
        Bs[lk4 + 2][lrow] = bv.z; Bs[lk4 + 3][lrow] = bv.w;
        __syncthreads();

#pragma unroll
        for (int k = 0; k < BK; ++k) {
            float ra[8], rb[8];
            *(float4*)(ra)     = *(const float4*)(&As[k][tr]);
            *(float4*)(ra + 4) = *(const float4*)(&As[k][tr + 4]);
            *(float4*)(rb)     = *(const float4*)(&Bs[k][tc]);
            *(float4*)(rb + 4) = *(const float4*)(&Bs[k][tc + 4]);
#pragma unroll
            for (int i = 0; i < 8; ++i)
#pragma unroll
                for (int j = 0; j < 8; ++j)
                    acc[i][j] = fmaf(ra[i], rb[j], acc[i][j]);
        }
        __syncthreads();
    }

    float bb[8];
#pragma unroll
    for (int j = 0; j < 8; ++j) {
        float b = bias1[bn + tc + j];
        if (TWO_BIAS) b += bias2[bn + tc + j];
        bb[j] = b;
    }
#pragma unroll
    for (int i = 0; i < 8; ++i) {
        float* cp = C + (size_t)(bm + tr + i) * N + bn + tc;
        float v[8];
#pragma unroll
        for (int j = 0; j < 8; ++j) {
            float x = acc[i][j] + bb[j];
            v[j] = RELU ? fmaxf(x, 0.f) : x;
        }
        *(float4*)(cp)     = *(float4*)(v);
        *(float4*)(cp + 4) = *(float4*)(v + 4);
    }
}

// ---------------------------------------------------------------------------
// Persistent recurrence kernel.
// Grid = 128 blocks (16 n-tiles x 8 k-slices), 256 threads.
// Each block keeps its W_hh tile [64 cols x 128 k] in DYNAMIC smem for all
// 511 steps. Per step: stage relu(S[t-1]) k-slice into smem, compute 64x64
// partial with packed f32x2 FMAs, atomicAdd into S[t], then grid barrier.
// ---------------------------------------------------------------------------
__global__ void __launch_bounds__(256)
rnn_persist(float* __restrict__ hid, const float* __restrict__ Whh)
{
    extern __shared__ float smem[];
    float (*Ws)[WS_STRIDE] = (float (*)[WS_STRIDE])smem;                    // [k][col]
    float (*Hs)[HS_STRIDE] = (float (*)[HS_STRIDE])(smem + 128 * WS_STRIDE); // [k][row]

    const int tid   = threadIdx.x;
    const int nbase = (blockIdx.x % NTILE) * 64;
    const int kbase = (blockIdx.x / NTILE) * 128;

    // ---- load W_hh tile once: cols [nbase, nbase+64), k [kbase, kbase+128)
    {
        const int col = tid >> 2;             // 0..63
#pragma unroll
        for (int it = 0; it < 8; ++it) {
            const int kg = (tid & 3) + it * 4;  // 0..31
            const int k4 = kg * 4;
            float4 w = *(const float4*)(Whh + (size_t)(nbase + col) * NHID + kbase + k4);
            Ws[k4 + 0][col] = w.x; Ws[k4 + 1][col] = w.y;
            Ws[k4 + 2][col] = w.z; Ws[k4 + 3][col] = w.w;
        }
    }
    __syncthreads();

    // replay-safe barrier base: epoch bumped by the preceding tiny kernel
    const unsigned long long base =
        (g_epoch - 1ULL) * (unsigned long long)NSTEPS * GRID_P;

    const int r0 = (tid >> 5) * 8;   // warp = one 8-row group (broadcast h)
    const int c0 = (tid & 31) * 2;   // lane = one col pair

    for (int t = 1; t < T_STEPS; ++t) {
        const float* Sprev = hid + (size_t)(t - 1) * B_SZ * NHID;
        float*       Scur  = hid + (size_t)t * B_SZ * NHID;

        // ---- stage relu(S[t-1]) slice [64 rows x 128 k] into Hs[k][row]
        {
            const int row = tid >> 2;           // 0..63
#pragma unroll
            for (int it = 0; it < 8; ++it) {
                const int kg = (tid & 3) + it * 4;
                const int k4 = kg * 4;
                float4 v = __ldcg((const float4*)(Sprev + (size_t)row * NHID + kbase + k4));
                Hs[k4 + 0][row] = fmaxf(v.x, 0.f);
                Hs[k4 + 1][row] = fmaxf(v.y, 0.f);
                Hs[k4 + 2][row] = fmaxf(v.z, 0.f);
                Hs[k4 + 3][row] = fmaxf(v.w, 0.f);
            }
        }
        __syncthreads();

        // ---- 64x64 partial over this 128-k slice, packed f32x2 FMAs
        unsigned long long acc[4][2];
#pragma unroll
        for (int i = 0; i < 4; ++i) { acc[i][0] = 0ULL; acc[i][1] = 0ULL; }

#pragma unroll 8
        for (int k = 0; k < 128; ++k) {
            // h row pairs {r0,r0+1},{r0+2,r0+3},... (broadcast across warp)
            ulonglong2 ha = *(const ulonglong2*)(&Hs[k][r0]);
            ulonglong2 hb = *(const ulonglong2*)(&Hs[k][r0 + 4]);
            float2 w = *(const float2*)(&Ws[k][c0]);
            unsigned int wxi = __float_as_uint(w.x);
            unsigned int wyi = __float_as_uint(w.y);
            unsigned long long w0, w1;
            asm("mov.b64 %0, {%1, %1};" : "=l"(w0) : "r"(wxi));
            asm("mov.b64 %0, {%1, %1};" : "=l"(w1) : "r"(wyi));
            FMA2(acc[0][0], ha.x, w0); FMA2(acc[0][1], ha.x, w1);
            FMA2(acc[1][0], ha.y, w0); FMA2(acc[1][1], ha.y, w1);
            FMA2(acc[2][0], hb.x, w0); FMA2(acc[2][1], hb.x, w1);
            FMA2(acc[3][0], hb.y, w0); FMA2(acc[3][1], hb.y, w1);
        }

        // ---- combine k-slice partials into S[t]
#pragma unroll
        for (int i = 0; i < 4; ++i) {
#pragma unroll
            for (int j = 0; j < 2; ++j) {
                unsigned long long a = acc[i][j];
                float flo = __uint_as_float((unsigned int)(a & 0xffffffffu));
                float fhi = __uint_as_float((unsigned int)(a >> 32));
                float* d0 = Scur + (size_t)(r0 + 2 * i) * NHID + nbase + c0 + j;
                atomicAdd(d0, flo);
                atomicAdd(d0 + NHID, fhi);
            }
        }

        // ---- grid barrier (monotonic counter, replay-safe target)
        __syncthreads();
        if (tid == 0) {
            __threadfence();
            atomicAdd(&g_bar, 1ULL);
            const unsigned long long target = base + (unsigned long long)t * GRID_P;
            while (*(volatile unsigned long long*)&g_bar < target) { }
            __threadfence();
        }
        __syncthreads();
    }
}

// ---------------------------------------------------------------------------
// In-place relu over hiddens (S -> h = relu(S)).
// ---------------------------------------------------------------------------
__global__ void relu_ip(float* __restrict__ p, int n4)
{
    int stride = gridDim.x * blockDim.x;
    for (int i = blockIdx.x * blockDim.x + threadIdx.x; i < n4; i += stride) {
        float4 v = ((float4*)p)[i];
        v.x = fmaxf(v.x, 0.f);
        v.y = fmaxf(v.y, 0.f);
        v.z = fmaxf(v.z, 0.f);
        v.w = fmaxf(v.w, 0.f);
        ((float4*)p)[i] = v;
    }
}

// ---------------------------------------------------------------------------
extern "C" void kernel_launch(void* const* d_in, const int* in_sizes, int n_in,
                              void* d_out, int out_size)
{
    const float* input = (const float*)d_in[0];
    // d_in[1] = length (fixed 512)
    const float* W_in  = (const float*)d_in[2];
    const float* b_in  = (const float*)d_in[3];
    const float* W_ih  = (const float*)d_in[4];
    const float* b_ih  = (const float*)d_in[5];
    const float* W_hh  = (const float*)d_in[6];
    const float* b_hh  = (const float*)d_in[7];
    const float* W_out = (const float*)d_in[8];
    const float* b_out = (const float*)d_in[9];

    float* hid  = (float*)d_out;                 // [T*B, NHID]
    float* outp = hid + (size_t)MROWS * NHID;    // [T*B, NOUT]

    float* Xp = nullptr;
    cudaGetSymbolAddress((void**)&Xp, g_X);

    // allow >48KB dynamic smem for the persistent kernel (host-side, capture-safe)
    static bool attr_set = false;
    if (!attr_set) {
        cudaFuncSetAttribute(rnn_persist,
                             cudaFuncAttributeMaxDynamicSharedMemorySize,
                             SMEM_BYTES);
        attr_set = true;
    }

    dim3 blk(256);

    // Phase A: X = relu(IN @ W_in^T + b_in)
    sgemm_nt<true, false><<<dim3(NHID / 128, MROWS / 128), blk>>>(
        input, W_in, b_in, nullptr, Xp, MROWS, NHID, NIN);

    // Phase B: S = X @ W_ih^T + b_ih + b_hh  (per-step U_t, in-place in hid)
    sgemm_nt<false, true><<<dim3(NHID / 128, MROWS / 128), blk>>>(
        Xp, W_ih, b_ih, b_hh, hid, MROWS, NHID, NHID);

    // Phase C: persistent recurrence (one launch for all 511 steps)
    epoch_bump<<<1, 1>>>();
    rnn_persist<<<GRID_P, blk, SMEM_BYTES>>>(hid, W_hh);

    // Relu fixup: hiddens = relu(S)
    relu_ip<<<8192, 256>>>(hid, (int)((size_t)MROWS * NHID / 4));

    // Phase D: outputs = H @ W_out^T + b_out
    sgemm_nt<false, false><<<dim3(NOUT / 128, MROWS / 128), blk>>>(
        hid, W_out, b_out, nullptr, outp, MROWS, NOUT, NHID);
}

// round 4
// speedup vs baseline: 1.3214x; 1.0332x over previous
#include <cuda_runtime.h>
#include <cstdint>

#define T_STEPS 512
#define B_SZ    64
#define NIN     256
#define NHID    1024
#define NOUT    256
#define MROWS   (T_STEPS * B_SZ)   // 32768

#define NTILE   16                 // n-tiles of 64 cols
#define KSLICE  8                  // k-slices of 128 k
#define GRID_P  (NTILE * KSLICE)   // 128 persistent blocks
#define NSTEPS  511                // sequential recurrence steps

#define WS_STRIDE 66               // floats per Ws row (8B-aligned float2 reads)
#define HS_STRIDE 68               // floats per Hs row (16B-aligned u64x2 reads)
#define SMEM_BYTES ((128 * WS_STRIDE + 128 * HS_STRIDE) * 4)   // 68608

// 128 MB scratch for X = relu(IN @ W_in^T + b_in)
__device__ float g_X[(size_t)MROWS * NHID];

// persistent-kernel synchronization state (monotonic, never reset)
__device__ unsigned long long g_epoch;
__device__ unsigned long long g_bar;

__global__ void epoch_bump() { g_epoch += 1ULL; }

// packed fp32x2 FMA (Blackwell): acc = a*b + acc, lane-wise on 2 floats
#define FMA2(acc, a, b) \
    asm volatile("fma.rn.f32x2 %0, %1, %2, %0;" : "+l"(acc) : "l"(a), "l"(b))

// duplicate one fp32 into both lanes of a packed f32x2 register
#define DUP2(dst, f) do {                                   \
    unsigned int _u = __float_as_uint(f);                   \
    asm("mov.b64 %0, {%1, %1};" : "=l"(dst) : "r"(_u));     \
} while (0)

// ---------------------------------------------------------------------------
// fp32 GEMM with packed f32x2 FMAs:
//   C[M,N] = act( A[M,K] @ Bw[N,K]^T + bias1 (+ bias2) )
// 128x128 block tile, BK=8, 256 threads.
// Micro-tile: 4 row-pairs x 8 cols per thread (32 FFMA2 per k).
// A-side pairs come packed directly from ulonglong2 smem loads; B-side values
// are duplicated into both lanes via mov.b64 (ALU pipe, non-binding).
// One-tile register prefetch hides the global-load latency.
// ---------------------------------------------------------------------------
template <bool RELU, bool TWO_BIAS>
__global__ void __launch_bounds__(256)
sgemm_nt(const float* __restrict__ A, const float* __restrict__ Bw,
         const float* __restrict__ bias1, const float* __restrict__ bias2,
         float* __restrict__ C, int M, int N, int K)
{
    const int BM = 128, BN = 128, BK = 8;
    __shared__ float As[BK][BM + 4];   // stride 132 floats (528B, 16B-aligned)
    __shared__ float Bs[BK][BN + 4];

    const int bm  = blockIdx.y * BM;
    const int bn  = blockIdx.x * BN;
    const int tid = threadIdx.x;

    // global loader mapping: 256 threads load 128 rows x 8 k as float4
    const int lrow = tid >> 1;
    const int lk4  = (tid & 1) * 4;
    const float* Aptr = A  + (size_t)(bm + lrow) * K + lk4;
    const float* Bptr = Bw + (size_t)(bn + lrow) * K + lk4;

    // compute mapping: 16x16 thread grid, 8 rows (4 pairs) x 8 cols
    const int tr = (tid >> 4) * 8;
    const int tc = (tid & 15) * 8;

    unsigned long long acc2[4][8];
#pragma unroll
    for (int p = 0; p < 4; ++p)
#pragma unroll
        for (int j = 0; j < 8; ++j) acc2[p][j] = 0ULL;

    // prefetch first tile
    float4 av = *(const float4*)(Aptr);
    float4 bv = *(const float4*)(Bptr);

    for (int k0 = 0; k0 < K; k0 += BK) {
        As[lk4 + 0][lrow] = av.x; As[lk4 + 1][lrow] = av.y;
        As[lk4 + 2][lrow] = av.z; As[lk4 + 3][lrow] = av.w;
        Bs[lk4 + 0][lrow] = bv.x; Bs[lk4 + 1][lrow] = bv.y;
        Bs[lk4 + 2][lrow] = bv.z; Bs[lk4 + 3][lrow] = bv.w;
        __syncthreads();

        // issue next tile's global loads before the compute block
        if (k0 + BK < K) {
            av = *(const float4*)(Aptr + k0 + BK);
            bv = *(const float4*)(Bptr + k0 + BK);
        }

#pragma unroll
        for (int k = 0; k < BK; ++k) {
            // 4 packed row-pairs of A (rows tr..tr+7)
            ulonglong2 a01 = *(const ulonglong2*)(&As[k][tr]);
            ulonglong2 a23 = *(const ulonglong2*)(&As[k][tr + 4]);
            // 8 B values for cols tc..tc+7
            float4 b0 = *(const float4*)(&Bs[k][tc]);
            float4 b1 = *(const float4*)(&Bs[k][tc + 4]);
            unsigned long long bd[8];
            DUP2(bd[0], b0.x); DUP2(bd[1], b0.y);
            DUP2(bd[2], b0.z); DUP2(bd[3], b0.w);
            DUP2(bd[4], b1.x); DUP2(bd[5], b1.y);
            DUP2(bd[6], b1.z); DUP2(bd[7], b1.w);
#pragma unroll
            for (int j = 0; j < 8; ++j) {
                FMA2(acc2[0][j], a01.x, bd[j]);
                FMA2(acc2[1][j], a01.y, bd[j]);
                FMA2(acc2[2][j], a23.x, bd[j]);
                FMA2(acc2[3][j], a23.y, bd[j]);
            }
        }
        __syncthreads();
    }

    // epilogue: bias (+bias2) (+relu), vectorized stores
    float bb[8];
#pragma unroll
    for (int j = 0; j < 8; ++j) {
        float b = bias1[bn + tc + j];
        if (TWO_BIAS) b += bias2[bn + tc + j];
        bb[j] = b;
    }
#pragma unroll
    for (int p = 0; p < 4; ++p) {
        float vlo[8], vhi[8];
#pragma unroll
        for (int j = 0; j < 8; ++j) {
            unsigned long long a = acc2[p][j];
            float lo = __uint_as_float((unsigned int)(a & 0xffffffffu));
            float hi = __uint_as_float((unsigned int)(a >> 32));
            lo += bb[j]; hi += bb[j];
            vlo[j] = RELU ? fmaxf(lo, 0.f) : lo;
            vhi[j] = RELU ? fmaxf(hi, 0.f) : hi;
        }
        float* cp0 = C + (size_t)(bm + tr + 2 * p)     * N + bn + tc;
        float* cp1 = C + (size_t)(bm + tr + 2 * p + 1) * N + bn + tc;
        *(float4*)(cp0)     = *(float4*)(vlo);
        *(float4*)(cp0 + 4) = *(float4*)(vlo + 4);
        *(float4*)(cp1)     = *(float4*)(vhi);
        *(float4*)(cp1 + 4) = *(float4*)(vhi + 4);
    }
}

// ---------------------------------------------------------------------------
// Persistent recurrence kernel (unchanged from R3 — passing).
// Grid = 128 blocks (16 n-tiles x 8 k-slices), 256 threads.
// ---------------------------------------------------------------------------
__global__ void __launch_bounds__(256)
rnn_persist(float* __restrict__ hid, const float* __restrict__ Whh)
{
    extern __shared__ float smem[];
    float (*Ws)[WS_STRIDE] = (float (*)[WS_STRIDE])smem;                     // [k][col]
    float (*Hs)[HS_STRIDE] = (float (*)[HS_STRIDE])(smem + 128 * WS_STRIDE); // [k][row]

    const int tid   = threadIdx.x;
    const int nbase = (blockIdx.x % NTILE) * 64;
    const int kbase = (blockIdx.x / NTILE) * 128;

    // ---- load W_hh tile once: cols [nbase, nbase+64), k [kbase, kbase+128)
    {
        const int col = tid >> 2;
#pragma unroll
        for (int it = 0; it < 8; ++it) {
            const int kg = (tid & 3) + it * 4;
            const int k4 = kg * 4;
            float4 w = *(const float4*)(Whh + (size_t)(nbase + col) * NHID + kbase + k4);
            Ws[k4 + 0][col] = w.x; Ws[k4 + 1][col] = w.y;
            Ws[k4 + 2][col] = w.z; Ws[k4 + 3][col] = w.w;
        }
    }
    __syncthreads();

    const unsigned long long base =
        (g_epoch - 1ULL) * (unsigned long long)NSTEPS * GRID_P;

    const int r0 = (tid >> 5) * 8;   // warp = one 8-row group (broadcast h)
    const int c0 = (tid & 31) * 2;   // lane = one col pair

    for (int t = 1; t < T_STEPS; ++t) {
        const float* Sprev = hid + (size_t)(t - 1) * B_SZ * NHID;
        float*       Scur  = hid + (size_t)t * B_SZ * NHID;

        // ---- stage relu(S[t-1]) slice [64 rows x 128 k] into Hs[k][row]
        {
            const int row = tid >> 2;
#pragma unroll
            for (int it = 0; it < 8; ++it) {
                const int kg = (tid & 3) + it * 4;
                const int k4 = kg * 4;
                float4 v = __ldcg((const float4*)(Sprev + (size_t)row * NHID + kbase + k4));
                Hs[k4 + 0][row] = fmaxf(v.x, 0.f);
                Hs[k4 + 1][row] = fmaxf(v.y, 0.f);
                Hs[k4 + 2][row] = fmaxf(v.z, 0.f);
                Hs[k4 + 3][row] = fmaxf(v.w, 0.f);
            }
        }
        __syncthreads();

        // ---- 64x64 partial over this 128-k slice, packed f32x2 FMAs
        unsigned long long acc[4][2];
#pragma unroll
        for (int i = 0; i < 4; ++i) { acc[i][0] = 0ULL; acc[i][1] = 0ULL; }

#pragma unroll 8
        for (int k = 0; k < 128; ++k) {
            ulonglong2 ha = *(const ulonglong2*)(&Hs[k][r0]);
            ulonglong2 hb = *(const ulonglong2*)(&Hs[k][r0 + 4]);
            float2 w = *(const float2*)(&Ws[k][c0]);
            unsigned long long w0, w1;
            DUP2(w0, w.x);
            DUP2(w1, w.y);
            FMA2(acc[0][0], ha.x, w0); FMA2(acc[0][1], ha.x, w1);
            FMA2(acc[1][0], ha.y, w0); FMA2(acc[1][1], ha.y, w1);
            FMA2(acc[2][0], hb.x, w0); FMA2(acc[2][1], hb.x, w1);
            FMA2(acc[3][0], hb.y, w0); FMA2(acc[3][1], hb.y, w1);
        }

        // ---- combine k-slice partials into S[t]
#pragma unroll
        for (int i = 0; i < 4; ++i) {
#pragma unroll
            for (int j = 0; j < 2; ++j) {
                unsigned long long a = acc[i][j];
                float flo = __uint_as_float((unsigned int)(a & 0xffffffffu));
                float fhi = __uint_as_float((unsigned int)(a >> 32));
                float* d0 = Scur + (size_t)(r0 + 2 * i) * NHID + nbase + c0 + j;
                atomicAdd(d0, flo);
                atomicAdd(d0 + NHID, fhi);
            }
        }

        // ---- grid barrier (monotonic counter, replay-safe target)
        __syncthreads();
        if (tid == 0) {
            __threadfence();
            atomicAdd(&g_bar, 1ULL);
            const unsigned long long target = base + (unsigned long long)t * GRID_P;
            while (*(volatile unsigned long long*)&g_bar < target) { }
            __threadfence();
        }
        __syncthreads();
    }
}

// ---------------------------------------------------------------------------
// In-place relu over hiddens (S -> h = relu(S)).
// ---------------------------------------------------------------------------
__global__ void relu_ip(float* __restrict__ p, int n4)
{
    int stride = gridDim.x * blockDim.x;
    for (int i = blockIdx.x * blockDim.x + threadIdx.x; i < n4; i += stride) {
        float4 v = ((float4*)p)[i];
        v.x = fmaxf(v.x, 0.f);
        v.y = fmaxf(v.y, 0.f);
        v.z = fmaxf(v.z, 0.f);
        v.w = fmaxf(v.w, 0.f);
        ((float4*)p)[i] = v;
    }
}

// ---------------------------------------------------------------------------
extern "C" void kernel_launch(void* const* d_in, const int* in_sizes, int n_in,
                              void* d_out, int out_size)
{
    const float* input = (const float*)d_in[0];
    // d_in[1] = length (fixed 512)
    const float* W_in  = (const float*)d_in[2];
    const float* b_in  = (const float*)d_in[3];
    const float* W_ih  = (const float*)d_in[4];
    const float* b_ih  = (const float*)d_in[5];
    const float* W_hh  = (const float*)d_in[6];
    const float* b_hh  = (const float*)d_in[7];
    const float* W_out = (const float*)d_in[8];
    const float* b_out = (const float*)d_in[9];

    float* hid  = (float*)d_out;                 // [T*B, NHID]
    float* outp = hid + (size_t)MROWS * NHID;    // [T*B, NOUT]

    float* Xp = nullptr;
    cudaGetSymbolAddress((void**)&Xp, g_X);

    // allow >48KB dynamic smem for the persistent kernel (idempotent, capture-safe)
    cudaFuncSetAttribute(rnn_persist,
                         cudaFuncAttributeMaxDynamicSharedMemorySize,
                         SMEM_BYTES);

    dim3 blk(256);

    // Phase A: X = relu(IN @ W_in^T + b_in)
    sgemm_nt<true, false><<<dim3(NHID / 128, MROWS / 128), blk>>>(
        input, W_in, b_in, nullptr, Xp, MROWS, NHID, NIN);

    // Phase B: S = X @ W_ih^T + b_ih + b_hh  (per-step U_t, in-place in hid)
    sgemm_nt<false, true><<<dim3(NHID / 128, MROWS / 128), blk>>>(
        Xp, W_ih, b_ih, b_hh, hid, MROWS, NHID, NHID);

    // Phase C: persistent recurrence (one launch for all 511 steps)
    epoch_bump<<<1, 1>>>();
    rnn_persist<<<GRID_P, blk, SMEM_BYTES>>>(hid, W_hh);

    // Relu fixup: hiddens = relu(S)
    relu_ip<<<8192, 256>>>(hid, (int)((size_t)MROWS * NHID / 4));

    // Phase D: outputs = H @ W_out^T + b_out
    sgemm_nt<false, false><<<dim3(NOUT / 128, MROWS / 128), blk>>>(
        hid, W_out, b_out, nullptr, outp, MROWS, NOUT, NHID);
}

// round 6
// speedup vs baseline: 1.4175x; 1.0727x over previous
#include <cuda_runtime.h>
#include <cstdint>

#define T_STEPS 512
#define B_SZ    64
#define NIN     256
#define NHID    1024
#define NOUT    256
#define MROWS   (T_STEPS * B_SZ)   // 32768

#define NTILE   16                 // n-tiles of 64 cols
#define KSLICE  8                  // k-slices of 128 k
#define GRID_P  (NTILE * KSLICE)   // 128 persistent blocks
#define NSTEPS  511                // sequential recurrence steps

#define WS_STRIDE 66               // floats per Ws row (8B-aligned float2 reads)
#define HS_STRIDE 68               // floats per Hs row (16B-aligned u64x2 reads)
#define SMEM_BYTES ((128 * WS_STRIDE + 128 * HS_STRIDE) * 4)   // 68608

// 128 MB scratch for X = relu(IN @ W_in^T + b_in)
__device__ float g_X[(size_t)MROWS * NHID];

// persistent-kernel synchronization state (monotonic, never reset)
__device__ unsigned long long g_epoch;
__device__ unsigned long long g_bar;

__global__ void epoch_bump() { g_epoch += 1ULL; }

// packed fp32x2 FMA (Blackwell): acc = a*b + acc, lane-wise on 2 floats
#define FMA2(acc, a, b) \
    asm volatile("fma.rn.f32x2 %0, %1, %2, %0;" : "+l"(acc) : "l"(a), "l"(b))

// duplicate one fp32 into both lanes of a packed f32x2 register
#define DUP2(dst, f) do {                                   \
    unsigned int _u = __float_as_uint(f);                   \
    asm("mov.b64 %0, {%1, %1};" : "=l"(dst) : "r"(_u));     \
} while (0)

// ---------------------------------------------------------------------------
// fp32 GEMM with packed f32x2 FMAs and 2-stage smem double buffering:
//   C[M,N] = act( A[M,K] @ Bw[N,K]^T + bias1 (+ bias2) )
// 128x128 block tile, BK=8, 256 threads, 4 row-pairs x 8 cols per thread.
// One __syncthreads per k-tile: STS of tile i+1 overlaps compute of tile i.
// ---------------------------------------------------------------------------
template <bool RELU, bool TWO_BIAS>
__global__ void __launch_bounds__(256)
sgemm_nt(const float* __restrict__ A, const float* __restrict__ Bw,
         const float* __restrict__ bias1, const float* __restrict__ bias2,
         float* __restrict__ C, int M, int N, int K)
{
    const int BM = 128, BN = 128, BK = 8;
    __shared__ float As[2][BK][BM + 4];
    __shared__ float Bs[2][BK][BN + 4];

    const int bm  = blockIdx.y * BM;
    const int bn  = blockIdx.x * BN;
    const int tid = threadIdx.x;

    // global loader mapping: 256 threads load 128 rows x 8 k as float4
    const int lrow = tid >> 1;
    const int lk4  = (tid & 1) * 4;
    const float* Aptr = A  + (size_t)(bm + lrow) * K + lk4;
    const float* Bptr = Bw + (size_t)(bn + lrow) * K + lk4;

    // compute mapping: 16x16 thread grid, 8 rows (4 pairs) x 8 cols
    const int tr = (tid >> 4) * 8;
    const int tc = (tid & 15) * 8;

    unsigned long long acc2[4][8];
#pragma unroll
    for (int p = 0; p < 4; ++p)
#pragma unroll
        for (int j = 0; j < 8; ++j) acc2[p][j] = 0ULL;

    // stage tile 0 into buffer 0
    {
        float4 av = *(const float4*)(Aptr);
        float4 bv = *(const float4*)(Bptr);
        As[0][lk4 + 0][lrow] = av.x; As[0][lk4 + 1][lrow] = av.y;
        As[0][lk4 + 2][lrow] = av.z; As[0][lk4 + 3][lrow] = av.w;
        Bs[0][lk4 + 0][lrow] = bv.x; Bs[0][lk4 + 1][lrow] = bv.y;
        Bs[0][lk4 + 2][lrow] = bv.z; Bs[0][lk4 + 3][lrow] = bv.w;
    }
    __syncthreads();

    int cur = 0;
    for (int k0 = 0; k0 < K; k0 += BK) {
        // prefetch next tile into registers
        float4 av, bv;
        const bool more = (k0 + BK < K);
        if (more) {
            av = *(const float4*)(Aptr + k0 + BK);
            bv = *(const float4*)(Bptr + k0 + BK);
        }

#pragma unroll
        for (int k = 0; k < BK; ++k) {
            ulonglong2 a01 = *(const ulonglong2*)(&As[cur][k][tr]);
            ulonglong2 a23 = *(const ulonglong2*)(&As[cur][k][tr + 4]);
            float4 b0 = *(const float4*)(&Bs[cur][k][tc]);
            float4 b1 = *(const float4*)(&Bs[cur][k][tc + 4]);
            unsigned long long bd[8];
            DUP2(bd[0], b0.x); DUP2(bd[1], b0.y);
            DUP2(bd[2], b0.z); DUP2(bd[3], b0.w);
            DUP2(bd[4], b1.x); DUP2(bd[5], b1.y);
            DUP2(bd[6], b1.z); DUP2(bd[7], b1.w);
#pragma unroll
            for (int j = 0; j < 8; ++j) {
                FMA2(acc2[0][j], a01.x, bd[j]);
                FMA2(acc2[1][j], a01.y, bd[j]);
                FMA2(acc2[2][j], a23.x, bd[j]);
                FMA2(acc2[3][j], a23.y, bd[j]);
            }
        }

        // stage next tile into the other buffer (overlaps compute above)
        if (more) {
            const int nxt = cur ^ 1;
            As[nxt][lk4 + 0][lrow] = av.x; As[nxt][lk4 + 1][lrow] = av.y;
            As[nxt][lk4 + 2][lrow] = av.z; As[nxt][lk4 + 3][lrow] = av.w;
            Bs[nxt][lk4 + 0][lrow] = bv.x; Bs[nxt][lk4 + 1][lrow] = bv.y;
            Bs[nxt][lk4 + 2][lrow] = bv.z; Bs[nxt][lk4 + 3][lrow] = bv.w;
        }
        __syncthreads();
        cur ^= 1;
    }

    // epilogue: bias (+bias2) (+relu), vectorized stores
    float bb[8];
#pragma unroll
    for (int j = 0; j < 8; ++j) {
        float b = bias1[bn + tc + j];
        if (TWO_BIAS) b += bias2[bn + tc + j];
        bb[j] = b;
    }
#pragma unroll
    for (int p = 0; p < 4; ++p) {
        float vlo[8], vhi[8];
#pragma unroll
        for (int j = 0; j < 8; ++j) {
            unsigned long long a = acc2[p][j];
            float lo = __uint_as_float((unsigned int)(a & 0xffffffffu));
            float hi = __uint_as_float((unsigned int)(a >> 32));
            lo += bb[j]; hi += bb[j];
            vlo[j] = RELU ? fmaxf(lo, 0.f) : lo;
            vhi[j] = RELU ? fmaxf(hi, 0.f) : hi;
        }
        float* cp0 = C + (size_t)(bm + tr + 2 * p)     * N + bn + tc;
        float* cp1 = C + (size_t)(bm + tr + 2 * p + 1) * N + bn + tc;
        *(float4*)(cp0)     = *(float4*)(vlo);
        *(float4*)(cp0 + 4) = *(float4*)(vlo + 4);
        *(float4*)(cp1)     = *(float4*)(vhi);
        *(float4*)(cp1 + 4) = *(float4*)(vhi + 4);
    }
}

// ---------------------------------------------------------------------------
// Persistent recurrence kernel, v2: release/acquire barrier, 2 syncs/step.
// Grid = 128 blocks (16 n-tiles x 8 k-slices), 256 threads.
// Each block keeps its W_hh tile [64 cols x 128 k] in smem for all 511 steps.
// ---------------------------------------------------------------------------
__global__ void __launch_bounds__(256)
rnn_persist(float* __restrict__ hid, const float* __restrict__ Whh)
{
    extern __shared__ float smem[];
    float (*Ws)[WS_STRIDE] = (float (*)[WS_STRIDE])smem;                     // [k][col]
    float (*Hs)[HS_STRIDE] = (float (*)[HS_STRIDE])(smem + 128 * WS_STRIDE); // [k][row]

    const int tid   = threadIdx.x;
    const int nbase = (blockIdx.x % NTILE) * 64;
    const int kbase = (blockIdx.x / NTILE) * 128;

    // ---- load W_hh tile once
    {
        const int col = tid >> 2;
#pragma unroll
        for (int it = 0; it < 8; ++it) {
            const int kg = (tid & 3) + it * 4;
            const int k4 = kg * 4;
            float4 w = *(const float4*)(Whh + (size_t)(nbase + col) * NHID + kbase + k4);
            Ws[k4 + 0][col] = w.x; Ws[k4 + 1][col] = w.y;
            Ws[k4 + 2][col] = w.z; Ws[k4 + 3][col] = w.w;
        }
    }
    __syncthreads();

    const unsigned long long base =
        (g_epoch - 1ULL) * (unsigned long long)NSTEPS * GRID_P;

    const int r0 = (tid >> 5) * 8;   // warp = one 8-row group (broadcast h)
    const int c0 = (tid & 31) * 2;   // lane = one col pair

    for (int t = 1; t < T_STEPS; ++t) {
        const float* Sprev = hid + (size_t)(t - 1) * B_SZ * NHID;
        float*       Scur  = hid + (size_t)t * B_SZ * NHID;

        // ---- wait for step t-1's REDs (skip for t==1: S[0] ready at launch)
        if (t > 1) {
            if (tid == 0) {
                const unsigned long long target =
                    base + (unsigned long long)(t - 1) * GRID_P;
                unsigned long long v;
                // relaxed poll (cheap), then one acquire read to synchronize
                do {
                    asm volatile("ld.relaxed.gpu.global.u64 %0, [%1];"
                                 : "=l"(v) : "l"(&g_bar) : "memory");
                } while (v < target);
                asm volatile("ld.acquire.gpu.global.u64 %0, [%1];"
                             : "=l"(v) : "l"(&g_bar) : "memory");
            }
            __syncthreads();
        }

        // ---- stage relu(S[t-1]) slice [64 rows x 128 k] into Hs[k][row]
        {
            const int row = tid >> 2;
#pragma unroll
            for (int it = 0; it < 8; ++it) {
                const int kg = (tid & 3) + it * 4;
                const int k4 = kg * 4;
                float4 v = __ldcg((const float4*)(Sprev + (size_t)row * NHID + kbase + k4));
                Hs[k4 + 0][row] = fmaxf(v.x, 0.f);
                Hs[k4 + 1][row] = fmaxf(v.y, 0.f);
                Hs[k4 + 2][row] = fmaxf(v.z, 0.f);
                Hs[k4 + 3][row] = fmaxf(v.w, 0.f);
            }
        }
        __syncthreads();

        // ---- 64x64 partial over this 128-k slice, packed f32x2 FMAs
        unsigned long long acc[4][2];
#pragma unroll
        for (int i = 0; i < 4; ++i) { acc[i][0] = 0ULL; acc[i][1] = 0ULL; }

#pragma unroll 8
        for (int k = 0; k < 128; ++k) {
            ulonglong2 ha = *(const ulonglong2*)(&Hs[k][r0]);
            ulonglong2 hb = *(const ulonglong2*)(&Hs[k][r0 + 4]);
            float2 w = *(const float2*)(&Ws[k][c0]);
            unsigned long long w0, w1;
            DUP2(w0, w.x);
            DUP2(w1, w.y);
            FMA2(acc[0][0], ha.x, w0); FMA2(acc[0][1], ha.x, w1);
            FMA2(acc[1][0], ha.y, w0); FMA2(acc[1][1], ha.y, w1);
            FMA2(acc[2][0], hb.x, w0); FMA2(acc[2][1], hb.x, w1);
            FMA2(acc[3][0], hb.y, w0); FMA2(acc[3][1], hb.y, w1);
        }

        // ---- combine k-slice partials into S[t] (fire-and-forget REDs)
#pragma unroll
        for (int i = 0; i < 4; ++i) {
#pragma unroll
            for (int j = 0; j < 2; ++j) {
                unsigned long long a = acc[i][j];
                float flo = __uint_as_float((unsigned int)(a & 0xffffffffu));
                float fhi = __uint_as_float((unsigned int)(a >> 32));
                float* d0 = Scur + (size_t)(r0 + 2 * i) * NHID + nbase + c0 + j;
                atomicAdd(d0, flo);
                atomicAdd(d0 + NHID, fhi);
            }
        }

        // ---- publish: block sync orders all threads' REDs, then release-add
        __syncthreads();
        if (tid == 0) {
            asm volatile("red.release.gpu.global.add.u64 [%0], %1;"
                         :: "l"(&g_bar), "l"(1ULL) : "memory");
        }
    }
}

// ---------------------------------------------------------------------------
// In-place relu over hiddens (S -> h = relu(S)).
// ---------------------------------------------------------------------------
__global__ void relu_ip(float* __restrict__ p, int n4)
{
    int stride = gridDim.x * blockDim.x;
    for (int i = blockIdx.x * blockDim.x + threadIdx.x; i < n4; i += stride) {
        float4 v = ((float4*)p)[i];
        v.x = fmaxf(v.x, 0.f);
        v.y = fmaxf(v.y, 0.f);
        v.z = fmaxf(v.z, 0.f);
        v.w = fmaxf(v.w, 0.f);
        ((float4*)p)[i] = v;
    }
}

// ---------------------------------------------------------------------------
extern "C" void kernel_launch(void* const* d_in, const int* in_sizes, int n_in,
                              void* d_out, int out_size)
{
    const float* input = (const float*)d_in[0];
    // d_in[1] = length (fixed 512)
    const float* W_in  = (const float*)d_in[2];
    const float* b_in  = (const float*)d_in[3];
    const float* W_ih  = (const float*)d_in[4];
    const float* b_ih  = (const float*)d_in[5];
    const float* W_hh  = (const float*)d_in[6];
    const float* b_hh  = (const float*)d_in[7];
    const float* W_out = (const float*)d_in[8];
    const float* b_out = (const float*)d_in[9];

    float* hid  = (float*)d_out;                 // [T*B, NHID]
    float* outp = hid + (size_t)MROWS * NHID;    // [T*B, NOUT]

    float* Xp = nullptr;
    cudaGetSymbolAddress((void**)&Xp, g_X);

    // allow >48KB dynamic smem for the persistent kernel (idempotent, capture-safe)
    cudaFuncSetAttribute(rnn_persist,
                         cudaFuncAttributeMaxDynamicSharedMemorySize,
                         SMEM_BYTES);

    dim3 blk(256);

    // Phase A: X = relu(IN @ W_in^T + b_in)
    sgemm_nt<true, false><<<dim3(NHID / 128, MROWS / 128), blk>>>(
        input, W_in, b_in, nullptr, Xp, MROWS, NHID, NIN);

    // Phase B: S = X @ W_ih^T + b_ih + b_hh  (per-step U_t, in-place in hid)
    sgemm_nt<false, true><<<dim3(NHID / 128, MROWS / 128), blk>>>(
        Xp, W_ih, b_ih, b_hh, hid, MROWS, NHID, NHID);

    // Phase C: persistent recurrence (one launch for all 511 steps)
    epoch_bump<<<1, 1>>>();
    rnn_persist<<<GRID_P, blk, SMEM_BYTES>>>(hid, W_hh);

    // Relu fixup: hiddens = relu(S)
    relu_ip<<<8192, 256>>>(hid, (int)((size_t)MROWS * NHID / 4));

    // Phase D: outputs = H @ W_out^T + b_out
    sgemm_nt<false, false><<<dim3(NOUT / 128, MROWS / 128), blk>>>(
        hid, W_out, b_out, nullptr, outp, MROWS, NOUT, NHID);
}

// round 7
// speedup vs baseline: 1.4311x; 1.0096x over previous
#include <cuda_runtime.h>
#include <cstdint>

#define T_STEPS 512
#define B_SZ    64
#define NIN     256
#define NHID    1024
#define NOUT    256
#define MROWS   (T_STEPS * B_SZ)   // 32768

#define NTILE   16                 // n-tiles of 64 cols
#define KSLICE  8                  // k-slices of 128 k
#define GRID_P  (NTILE * KSLICE)   // 128 persistent blocks

#define WS_STRIDE 66               // floats per Ws row (8B-aligned float2 reads)
#define HS_STRIDE 68               // floats per Hs row (16B-aligned u64x2 reads)
#define SMEM_BYTES ((128 * WS_STRIDE + 128 * HS_STRIDE) * 4)   // 68608

#define CNT_PAD 8                  // u32 stride per counter (32B, avoid sector thrash)

// 128 MB scratch for X = relu(IN @ W_in^T + b_in)
__device__ float g_X[(size_t)MROWS * NHID];

// fine-grained dependency counters: one per (step, n-tile), monotonic forever
__device__ unsigned int g_cnt[T_STEPS * NTILE * CNT_PAD];
__device__ unsigned long long g_epoch;

__global__ void epoch_bump() { g_epoch += 1ULL; }

// packed fp32x2 FMA (Blackwell): acc = a*b + acc, lane-wise on 2 floats
#define FMA2(acc, a, b) \
    asm volatile("fma.rn.f32x2 %0, %1, %2, %0;" : "+l"(acc) : "l"(a), "l"(b))

// duplicate one fp32 into both lanes of a packed f32x2 register
#define DUP2(dst, f) do {                                   \
    unsigned int _u = __float_as_uint(f);                   \
    asm("mov.b64 %0, {%1, %1};" : "=l"(dst) : "r"(_u));     \
} while (0)

// ---------------------------------------------------------------------------
// fp32 GEMM with packed f32x2 FMAs and 2-stage smem double buffering:
//   C[M,N] = act( A[M,K] @ Bw[N,K]^T + bias1 (+ bias2) )
// 128x128 block tile, BK=8, 256 threads, 4 row-pairs x 8 cols per thread.
// ---------------------------------------------------------------------------
template <bool RELU, bool TWO_BIAS>
__global__ void __launch_bounds__(256)
sgemm_nt(const float* __restrict__ A, const float* __restrict__ Bw,
         const float* __restrict__ bias1, const float* __restrict__ bias2,
         float* __restrict__ C, int M, int N, int K)
{
    const int BM = 128, BN = 128, BK = 8;
    __shared__ float As[2][BK][BM + 4];
    __shared__ float Bs[2][BK][BN + 4];

    const int bm  = blockIdx.y * BM;
    const int bn  = blockIdx.x * BN;
    const int tid = threadIdx.x;

    const int lrow = tid >> 1;
    const int lk4  = (tid & 1) * 4;
    const float* Aptr = A  + (size_t)(bm + lrow) * K + lk4;
    const float* Bptr = Bw + (size_t)(bn + lrow) * K + lk4;

    const int tr = (tid >> 4) * 8;
    const int tc = (tid & 15) * 8;

    unsigned long long acc2[4][8];
#pragma unroll
    for (int p = 0; p < 4; ++p)
#pragma unroll
        for (int j = 0; j < 8; ++j) acc2[p][j] = 0ULL;

    {
        float4 av = *(const float4*)(Aptr);
        float4 bv = *(const float4*)(Bptr);
        As[0][lk4 + 0][lrow] = av.x; As[0][lk4 + 1][lrow] = av.y;
        As[0][lk4 + 2][lrow] = av.z; As[0][lk4 + 3][lrow] = av.w;
        Bs[0][lk4 + 0][lrow] = bv.x; Bs[0][lk4 + 1][lrow] = bv.y;
        Bs[0][lk4 + 2][lrow] = bv.z; Bs[0][lk4 + 3][lrow] = bv.w;
    }
    __syncthreads();

    int cur = 0;
    for (int k0 = 0; k0 < K; k0 += BK) {
        float4 av, bv;
        const bool more = (k0 + BK < K);
        if (more) {
            av = *(const float4*)(Aptr + k0 + BK);
            bv = *(const float4*)(Bptr + k0 + BK);
        }

#pragma unroll
        for (int k = 0; k < BK; ++k) {
            ulonglong2 a01 = *(const ulonglong2*)(&As[cur][k][tr]);
            ulonglong2 a23 = *(const ulonglong2*)(&As[cur][k][tr + 4]);
            float4 b0 = *(const float4*)(&Bs[cur][k][tc]);
            float4 b1 = *(const float4*)(&Bs[cur][k][tc + 4]);
            unsigned long long bd[8];
            DUP2(bd[0], b0.x); DUP2(bd[1], b0.y);
            DUP2(bd[2], b0.z); DUP2(bd[3], b0.w);
            DUP2(bd[4], b1.x); DUP2(bd[5], b1.y);
            DUP2(bd[6], b1.z); DUP2(bd[7], b1.w);
#pragma unroll
            for (int j = 0; j < 8; ++j) {
                FMA2(acc2[0][j], a01.x, bd[j]);
                FMA2(acc2[1][j], a01.y, bd[j]);
                FMA2(acc2[2][j], a23.x, bd[j]);
                FMA2(acc2[3][j], a23.y, bd[j]);
            }
        }

        if (more) {
            const int nxt = cur ^ 1;
            As[nxt][lk4 + 0][lrow] = av.x; As[nxt][lk4 + 1][lrow] = av.y;
            As[nxt][lk4 + 2][lrow] = av.z; As[nxt][lk4 + 3][lrow] = av.w;
            Bs[nxt][lk4 + 0][lrow] = bv.x; Bs[nxt][lk4 + 1][lrow] = bv.y;
            Bs[nxt][lk4 + 2][lrow] = bv.z; Bs[nxt][lk4 + 3][lrow] = bv.w;
        }
        __syncthreads();
        cur ^= 1;
    }

    float bb[8];
#pragma unroll
    for (int j = 0; j < 8; ++j) {
        float b = bias1[bn + tc + j];
        if (TWO_BIAS) b += bias2[bn + tc + j];
        bb[j] = b;
    }
#pragma unroll
    for (int p = 0; p < 4; ++p) {
        float vlo[8], vhi[8];
#pragma unroll
        for (int j = 0; j < 8; ++j) {
            unsigned long long a = acc2[p][j];
            float lo = __uint_as_float((unsigned int)(a & 0xffffffffu));
            float hi = __uint_as_float((unsigned int)(a >> 32));
            lo += bb[j]; hi += bb[j];
            vlo[j] = RELU ? fmaxf(lo, 0.f) : lo;
            vhi[j] = RELU ? fmaxf(hi, 0.f) : hi;
        }
        float* cp0 = C + (size_t)(bm + tr + 2 * p)     * N + bn + tc;
        float* cp1 = C + (size_t)(bm + tr + 2 * p + 1) * N + bn + tc;
        *(float4*)(cp0)     = *(float4*)(vlo);
        *(float4*)(cp0 + 4) = *(float4*)(vlo + 4);
        *(float4*)(cp1)     = *(float4*)(vhi);
        *(float4*)(cp1 + 4) = *(float4*)(vhi + 4);
    }
}

// ---------------------------------------------------------------------------
// Persistent recurrence kernel, v3: fine-grained (step, n-tile) counters.
// A block on k-slice [kbase, kbase+128) waits only for the 2 n-tile counters
// covering its slice (8 producer arrivals each) — not the whole grid.
// float2 REDs halve the atomic count.
// ---------------------------------------------------------------------------
__global__ void __launch_bounds__(256)
rnn_persist(float* __restrict__ hid, const float* __restrict__ Whh)
{
    extern __shared__ float smem[];
    float (*Ws)[WS_STRIDE] = (float (*)[WS_STRIDE])smem;                     // [k][col]
    float (*Hs)[HS_STRIDE] = (float (*)[HS_STRIDE])(smem + 128 * WS_STRIDE); // [k][row]

    const int tid    = threadIdx.x;
    const int ntile  = blockIdx.x % NTILE;
    const int nbase  = ntile * 64;
    const int kbase  = (blockIdx.x / NTILE) * 128;
    const int j0     = kbase >> 6;          // first n-tile this slice reads
    // j1 = j0 + 1

    // ---- load W_hh tile once
    {
        const int col = tid >> 2;
#pragma unroll
        for (int it = 0; it < 8; ++it) {
            const int kg = (tid & 3) + it * 4;
            const int k4 = kg * 4;
            float4 w = *(const float4*)(Whh + (size_t)(nbase + col) * NHID + kbase + k4);
            Ws[k4 + 0][col] = w.x; Ws[k4 + 1][col] = w.y;
            Ws[k4 + 2][col] = w.z; Ws[k4 + 3][col] = w.w;
        }
    }
    __syncthreads();

    // per-epoch counter target: each (t, ntile) counter gains KSLICE per run
    const unsigned int target = (unsigned int)(g_epoch * KSLICE);

    const int r0 = (tid >> 5) * 8;   // warp = one 8-row group (broadcast h)
    const int c0 = (tid & 31) * 2;   // lane = one col pair

    for (int t = 1; t < T_STEPS; ++t) {
        const float* Sprev = hid + (size_t)(t - 1) * B_SZ * NHID;
        float*       Scur  = hid + (size_t)t * B_SZ * NHID;

        // ---- wait for the 2 producer counters of step t-1 (skip t==1)
        if (t > 1) {
            if (tid == 0 || tid == 32) {
                const int jj = (tid == 0) ? j0 : j0 + 1;
                const unsigned int* cp =
                    &g_cnt[((t - 1) * NTILE + jj) * CNT_PAD];
                unsigned int v;
                do {
                    asm volatile("ld.relaxed.gpu.global.u32 %0, [%1];"
                                 : "=r"(v) : "l"(cp) : "memory");
                } while (v < target);
                asm volatile("ld.acquire.gpu.global.u32 %0, [%1];"
                             : "=r"(v) : "l"(cp) : "memory");
            }
            __syncthreads();
        }

        // ---- stage relu(S[t-1]) slice [64 rows x 128 k] into Hs[k][row]
        {
            const int row = tid >> 2;
#pragma unroll
            for (int it = 0; it < 8; ++it) {
                const int kg = (tid & 3) + it * 4;
                const int k4 = kg * 4;
                float4 v = __ldcg((const float4*)(Sprev + (size_t)row * NHID + kbase + k4));
                Hs[k4 + 0][row] = fmaxf(v.x, 0.f);
                Hs[k4 + 1][row] = fmaxf(v.y, 0.f);
                Hs[k4 + 2][row] = fmaxf(v.z, 0.f);
                Hs[k4 + 3][row] = fmaxf(v.w, 0.f);
            }
        }
        __syncthreads();

        // ---- 64x64 partial over this 128-k slice, packed f32x2 FMAs
        unsigned long long acc[4][2];
#pragma unroll
        for (int i = 0; i < 4; ++i) { acc[i][0] = 0ULL; acc[i][1] = 0ULL; }

#pragma unroll 8
        for (int k = 0; k < 128; ++k) {
            ulonglong2 ha = *(const ulonglong2*)(&Hs[k][r0]);
            ulonglong2 hb = *(const ulonglong2*)(&Hs[k][r0 + 4]);
            float2 w = *(const float2*)(&Ws[k][c0]);
            unsigned long long w0, w1;
            DUP2(w0, w.x);
            DUP2(w1, w.y);
            FMA2(acc[0][0], ha.x, w0); FMA2(acc[0][1], ha.x, w1);
            FMA2(acc[1][0], ha.y, w0); FMA2(acc[1][1], ha.y, w1);
            FMA2(acc[2][0], hb.x, w0); FMA2(acc[2][1], hb.x, w1);
            FMA2(acc[3][0], hb.y, w0); FMA2(acc[3][1], hb.y, w1);
        }

        // ---- combine partials into S[t]: float2 REDs (cols c0, c0+1 per row)
#pragma unroll
        for (int i = 0; i < 4; ++i) {
            unsigned long long a0 = acc[i][0];   // rows (2i, 2i+1), col c0
            unsigned long long a1 = acc[i][1];   // rows (2i, 2i+1), col c0+1
            float lo0 = __uint_as_float((unsigned int)(a0 & 0xffffffffu));
            float hi0 = __uint_as_float((unsigned int)(a0 >> 32));
            float lo1 = __uint_as_float((unsigned int)(a1 & 0xffffffffu));
            float hi1 = __uint_as_float((unsigned int)(a1 >> 32));
            float* r_lo = Scur + (size_t)(r0 + 2 * i)     * NHID + nbase + c0;
            float* r_hi = Scur + (size_t)(r0 + 2 * i + 1) * NHID + nbase + c0;
            atomicAdd((float2*)r_lo, make_float2(lo0, lo1));
            atomicAdd((float2*)r_hi, make_float2(hi0, hi1));
        }

        // ---- publish this block's n-tile contribution for step t
        __syncthreads();
        if (tid == 0) {
            asm volatile("red.release.gpu.global.add.u32 [%0], %1;"
                         :: "l"(&g_cnt[(t * NTILE + ntile) * CNT_PAD]), "r"(1u)
                         : "memory");
        }
    }
}

// ---------------------------------------------------------------------------
// In-place relu over hiddens (S -> h = relu(S)).
// ---------------------------------------------------------------------------
__global__ void relu_ip(float* __restrict__ p, int n4)
{
    int stride = gridDim.x * blockDim.x;
    for (int i = blockIdx.x * blockDim.x + threadIdx.x; i < n4; i += stride) {
        float4 v = ((float4*)p)[i];
        v.x = fmaxf(v.x, 0.f);
        v.y = fmaxf(v.y, 0.f);
        v.z = fmaxf(v.z, 0.f);
        v.w = fmaxf(v.w, 0.f);
        ((float4*)p)[i] = v;
    }
}

// ---------------------------------------------------------------------------
extern "C" void kernel_launch(void* const* d_in, const int* in_sizes, int n_in,
                              void* d_out, int out_size)
{
    const float* input = (const float*)d_in[0];
    // d_in[1] = length (fixed 512)
    const float* W_in  = (const float*)d_in[2];
    const float* b_in  = (const float*)d_in[3];
    const float* W_ih  = (const float*)d_in[4];
    const float* b_ih  = (const float*)d_in[5];
    const float* W_hh  = (const float*)d_in[6];
    const float* b_hh  = (const float*)d_in[7];
    const float* W_out = (const float*)d_in[8];
    const float* b_out = (const float*)d_in[9];

    float* hid  = (float*)d_out;                 // [T*B, NHID]
    float* outp = hid + (size_t)MROWS * NHID;    // [T*B, NOUT]

    float* Xp = nullptr;
    cudaGetSymbolAddress((void**)&Xp, g_X);

    // allow >48KB dynamic smem for the persistent kernel (idempotent, capture-safe)
    cudaFuncSetAttribute(rnn_persist,
                         cudaFuncAttributeMaxDynamicSharedMemorySize,
                         SMEM_BYTES);

    dim3 blk(256);

    // Phase A: X = relu(IN @ W_in^T + b_in)
    sgemm_nt<true, false><<<dim3(NHID / 128, MROWS / 128), blk>>>(
        input, W_in, b_in, nullptr, Xp, MROWS, NHID, NIN);

    // Phase B: S = X @ W_ih^T + b_ih + b_hh  (per-step U_t, in-place in hid)
    sgemm_nt<false, true><<<dim3(NHID / 128, MROWS / 128), blk>>>(
        Xp, W_ih, b_ih, b_hh, hid, MROWS, NHID, NHID);

    // Phase C: persistent recurrence (one launch, fine-grained dependencies)
    epoch_bump<<<1, 1>>>();
    rnn_persist<<<GRID_P, blk, SMEM_BYTES>>>(hid, W_hh);

    // Relu fixup: hiddens = relu(S)
    relu_ip<<<8192, 256>>>(hid, (int)((size_t)MROWS * NHID / 4));

    // Phase D: outputs = H @ W_out^T + b_out
    sgemm_nt<false, false><<<dim3(NOUT / 128, MROWS / 128), blk>>>(
        hid, W_out, b_out, nullptr, outp, MROWS, NOUT, NHID);
}

// round 9
// speedup vs baseline: 2.0294x; 1.4180x over previous
#include <cuda_runtime.h>
#include <cstdint>

#define T_STEPS 512
#define B_SZ    64
#define NIN     256
#define NHID    1024
#define NOUT    256
#define MROWS   (T_STEPS * B_SZ)   // 32768

#define NTILE   16                 // recurrence n-tiles of 64 cols
#define KSLICE  8                  // recurrence k-slices of 128 k
#define GRID_P  (NTILE * KSLICE)   // 128 persistent blocks

#define WS_STRIDE 66
#define HS_STRIDE 68
#define SMEM_BYTES ((128 * WS_STRIDE + 128 * HS_STRIDE) * 4)   // 68608

#define CNT_PAD 8

// tgemm smem: A,B each [2][128][36] floats
#define TGS    36
#define TG_BUF (128 * TGS)                 // floats per buffer
#define TG_SMEM (4 * TG_BUF * 4)           // 2 bufs x (A+B) = 73728 bytes

// 128 MB scratch for X = relu(IN @ W_in^T + b_in)
__device__ float g_X[(size_t)MROWS * NHID];

// fine-grained dependency counters: one per (step, n-tile), monotonic forever
__device__ unsigned int g_cnt[T_STEPS * NTILE * CNT_PAD];
__device__ unsigned long long g_epoch;

__global__ void epoch_bump() { g_epoch += 1ULL; }

// packed fp32x2 FMA (recurrence kernel)
#define FMA2(acc, a, b) \
    asm volatile("fma.rn.f32x2 %0, %1, %2, %0;" : "+l"(acc) : "l"(a), "l"(b))
#define DUP2(dst, f) do {                                   \
    unsigned int _u = __float_as_uint(f);                   \
    asm("mov.b64 %0, {%1, %1};" : "=l"(dst) : "r"(_u));     \
} while (0)

// fp32 -> tf32 (round to nearest) ; result kept as fp32 bit pattern
#define TF32R(dst_f, src_f) do {                                      \
    uint32_t _t;                                                      \
    asm("cvt.rna.tf32.f32 %0, %1;" : "=r"(_t) : "f"(src_f));          \
    dst_f = __uint_as_float(_t);                                      \
} while (0)

// tf32 tensor-core mma: D(16x8) += A(16x8) * B(8x8), fp32 accum
#define MMA_TF32(d, a, b)                                                     \
    asm volatile(                                                             \
        "mma.sync.aligned.m16n8k8.row.col.f32.tf32.tf32.f32 "                 \
        "{%0,%1,%2,%3}, {%4,%5,%6,%7}, {%8,%9}, {%0,%1,%2,%3};"               \
        : "+f"((d)[0]), "+f"((d)[1]), "+f"((d)[2]), "+f"((d)[3])              \
        : "r"((a)[0]), "r"((a)[1]), "r"((a)[2]), "r"((a)[3]),                 \
          "r"((b)[0]), "r"((b)[1]))

// ===========================================================================
// tf32 mma.sync GEMM:  C[M,N] = act( A[M,K] @ Bw[N,K]^T + bias1 (+ bias2) )
// 128x128 block tile, BK=32, 256 threads (8 warps, 2x4 grid, 64x32 per warp).
// A,B staged as [row][k] stride-36 (conflict-free fragment loads), tf32
// rounding at staging time, double-buffered, one sync per k-tile.
// Requires M%128==0, N%128==0, K%32==0.
// ===========================================================================
template <bool RELU, bool TWO_BIAS>
__global__ void __launch_bounds__(256)
tgemm(const float* __restrict__ A, const float* __restrict__ Bw,
      const float* __restrict__ bias1, const float* __restrict__ bias2,
      float* __restrict__ C, int M, int N, int K)
{
    extern __shared__ float sm[];
    float* As = sm;                  // [2][128][36]
    float* Bs = sm + 2 * TG_BUF;     // [2][128][36]

    const int tid    = threadIdx.x;
    const int lane   = tid & 31;
    const int wid    = tid >> 5;
    const int warp_m = wid & 1;      // 0..1 -> 64 rows each
    const int warp_n = wid >> 1;     // 0..3 -> 32 cols each

    const int bm = blockIdx.y * 128;
    const int bn = blockIdx.x * 128;

    const float* Ag = A  + (size_t)bm * K;
    const float* Bg = Bw + (size_t)bn * K;

    // staging map: 4 iters, idx = tid + i*256 ; row = idx>>3 ; kq = (idx&7)*4
    float4 pa[4], pb[4];
#pragma unroll
    for (int i = 0; i < 4; ++i) {
        const int idx = tid + i * 256, row = idx >> 3, kq = (idx & 7) * 4;
        pa[i] = *(const float4*)(Ag + (size_t)row * K + kq);
        pb[i] = *(const float4*)(Bg + (size_t)row * K + kq);
    }
#pragma unroll
    for (int i = 0; i < 4; ++i) {
        const int idx = tid + i * 256, row = idx >> 3, kq = (idx & 7) * 4;
        float* dA = As + row * TGS + kq;
        float* dB = Bs + row * TGS + kq;
        TF32R(dA[0], pa[i].x); TF32R(dA[1], pa[i].y);
        TF32R(dA[2], pa[i].z); TF32R(dA[3], pa[i].w);
        TF32R(dB[0], pb[i].x); TF32R(dB[1], pb[i].y);
        TF32R(dB[2], pb[i].z); TF32R(dB[3], pb[i].w);
    }
    __syncthreads();

    // fragment base indices
    const int aRow = warp_m * 64 + (lane >> 2);   // + fm*16 (+8)
    const int aCol = lane & 3;                    // + k8*8 (+4)
    const int bRow = warp_n * 32 + (lane >> 2);   // + fn*8   (B stored [n][k])
    const int bCol = lane & 3;                    // + k8*8 (+4)

    float acc[4][4][4];
#pragma unroll
    for (int fm = 0; fm < 4; ++fm)
#pragma unroll
        for (int fn = 0; fn < 4; ++fn)
#pragma unroll
            for (int q = 0; q < 4; ++q) acc[fm][fn][q] = 0.f;

    int cur = 0;
    for (int k0 = 0; k0 < K; k0 += 32) {
        const bool more = (k0 + 32 < K);
        if (more) {
#pragma unroll
            for (int i = 0; i < 4; ++i) {
                const int idx = tid + i * 256, row = idx >> 3, kq = (idx & 7) * 4;
                pa[i] = *(const float4*)(Ag + (size_t)row * K + k0 + 32 + kq);
                pb[i] = *(const float4*)(Bg + (size_t)row * K + k0 + 32 + kq);
            }
        }

        const float* Ac = As + cur * TG_BUF;
        const float* Bc = Bs + cur * TG_BUF;
#pragma unroll
        for (int k8 = 0; k8 < 4; ++k8) {
            uint32_t af[4][4], bf[4][2];
#pragma unroll
            for (int fm = 0; fm < 4; ++fm) {
                const float* p = Ac + (aRow + fm * 16) * TGS + k8 * 8 + aCol;
                af[fm][0] = __float_as_uint(p[0]);
                af[fm][1] = __float_as_uint(p[8 * TGS]);
                af[fm][2] = __float_as_uint(p[4]);
                af[fm][3] = __float_as_uint(p[8 * TGS + 4]);
            }
#pragma unroll
            for (int fn = 0; fn < 4; ++fn) {
                const float* p = Bc + (bRow + fn * 8) * TGS + k8 * 8 + bCol;
                bf[fn][0] = __float_as_uint(p[0]);
                bf[fn][1] = __float_as_uint(p[4]);
            }
#pragma unroll
            for (int fm = 0; fm < 4; ++fm)
#pragma unroll
                for (int fn = 0; fn < 4; ++fn)
                    MMA_TF32(acc[fm][fn], af[fm], bf[fn]);
        }

        if (more) {
            const int nxt = cur ^ 1;
#pragma unroll
            for (int i = 0; i < 4; ++i) {
                const int idx = tid + i * 256, row = idx >> 3, kq = (idx & 7) * 4;
                float* dA = As + nxt * TG_BUF + row * TGS + kq;
                float* dB = Bs + nxt * TG_BUF + row * TGS + kq;
                TF32R(dA[0], pa[i].x); TF32R(dA[1], pa[i].y);
                TF32R(dA[2], pa[i].z); TF32R(dA[3], pa[i].w);
                TF32R(dB[0], pb[i].x); TF32R(dB[1], pb[i].y);
                TF32R(dB[2], pb[i].z); TF32R(dB[3], pb[i].w);
            }
        }
        __syncthreads();
        cur ^= 1;
    }

    // epilogue: c frag rows r, r+8 ; cols 2q, 2q+1 (contiguous pair)
#pragma unroll
    for (int fm = 0; fm < 4; ++fm) {
        const int r = bm + warp_m * 64 + fm * 16 + (lane >> 2);
#pragma unroll
        for (int fn = 0; fn < 4; ++fn) {
            const int c = bn + warp_n * 32 + fn * 8 + 2 * (lane & 3);
            float b0 = bias1[c], b1 = bias1[c + 1];
            if (TWO_BIAS) { b0 += bias2[c]; b1 += bias2[c + 1]; }
            float v0 = acc[fm][fn][0] + b0;
            float v1 = acc[fm][fn][1] + b1;
            float v2 = acc[fm][fn][2] + b0;
            float v3 = acc[fm][fn][3] + b1;
            if (RELU) {
                v0 = fmaxf(v0, 0.f); v1 = fmaxf(v1, 0.f);
                v2 = fmaxf(v2, 0.f); v3 = fmaxf(v3, 0.f);
            }
            *(float2*)(C + (size_t)r * N + c)       = make_float2(v0, v1);
            *(float2*)(C + (size_t)(r + 8) * N + c) = make_float2(v2, v3);
        }
    }
}

// ===========================================================================
// Persistent recurrence kernel (unchanged from R7 — passing).
// ===========================================================================
__global__ void __launch_bounds__(256)
rnn_persist(float* __restrict__ hid, const float* __restrict__ Whh)
{
    extern __shared__ float fsmem[];
    float (*Ws)[WS_STRIDE] = (float (*)[WS_STRIDE])fsmem;
    float (*Hs)[HS_STRIDE] = (float (*)[HS_STRIDE])(fsmem + 128 * WS_STRIDE);

    const int tid    = threadIdx.x;
    const int ntile  = blockIdx.x % NTILE;
    const int nbase  = ntile * 64;
    const int kbase  = (blockIdx.x / NTILE) * 128;
    const int j0     = kbase >> 6;

    {
        const int col = tid >> 2;
#pragma unroll
        for (int it = 0; it < 8; ++it) {
            const int kg = (tid & 3) + it * 4;
            const int k4 = kg * 4;
            float4 w = *(const float4*)(Whh + (size_t)(nbase + col) * NHID + kbase + k4);
            Ws[k4 + 0][col] = w.x; Ws[k4 + 1][col] = w.y;
            Ws[k4 + 2][col] = w.z; Ws[k4 + 3][col] = w.w;
        }
    }
    __syncthreads();

    const unsigned int target = (unsigned int)(g_epoch * KSLICE);
    const int r0 = (tid >> 5) * 8;
    const int c0 = (tid & 31) * 2;

    for (int t = 1; t < T_STEPS; ++t) {
        const float* Sprev = hid + (size_t)(t - 1) * B_SZ * NHID;
        float*       Scur  = hid + (size_t)t * B_SZ * NHID;

        if (t > 1) {
            if (tid == 0 || tid == 32) {
                const int jj = (tid == 0) ? j0 : j0 + 1;
                const unsigned int* cp = &g_cnt[((t - 1) * NTILE + jj) * CNT_PAD];
                unsigned int v;
                do {
                    asm volatile("ld.relaxed.gpu.global.u32 %0, [%1];"
                                 : "=r"(v) : "l"(cp) : "memory");
                } while (v < target);
                asm volatile("ld.acquire.gpu.global.u32 %0, [%1];"
                             : "=r"(v) : "l"(cp) : "memory");
            }
            __syncthreads();
        }

        {
            const int row = tid >> 2;
#pragma unroll
            for (int it = 0; it < 8; ++it) {
                const int kg = (tid & 3) + it * 4;
                const int k4 = kg * 4;
                float4 v = __ldcg((const float4*)(Sprev + (size_t)row * NHID + kbase + k4));
                Hs[k4 + 0][row] = fmaxf(v.x, 0.f);
                Hs[k4 + 1][row] = fmaxf(v.y, 0.f);
                Hs[k4 + 2][row] = fmaxf(v.z, 0.f);
                Hs[k4 + 3][row] = fmaxf(v.w, 0.f);
            }
        }
        __syncthreads();

        unsigned long long acc[4][2];
#pragma unroll
        for (int i = 0; i < 4; ++i) { acc[i][0] = 0ULL; acc[i][1] = 0ULL; }

#pragma unroll 8
        for (int k = 0; k < 128; ++k) {
            ulonglong2 ha = *(const ulonglong2*)(&Hs[k][r0]);
            ulonglong2 hb = *(const ulonglong2*)(&Hs[k][r0 + 4]);
            float2 w = *(const float2*)(&Ws[k][c0]);
            unsigned long long w0, w1;
            DUP2(w0, w.x);
            DUP2(w1, w.y);
            FMA2(acc[0][0], ha.x, w0); FMA2(acc[0][1], ha.x, w1);
            FMA2(acc[1][0], ha.y, w0); FMA2(acc[1][1], ha.y, w1);
            FMA2(acc[2][0], hb.x, w0); FMA2(acc[2][1], hb.x, w1);
            FMA2(acc[3][0], hb.y, w0); FMA2(acc[3][1], hb.y, w1);
        }

#pragma unroll
        for (int i = 0; i < 4; ++i) {
            unsigned long long a0 = acc[i][0];
            unsigned long long a1 = acc[i][1];
            float lo0 = __uint_as_float((unsigned int)(a0 & 0xffffffffu));
            float hi0 = __uint_as_float((unsigned int)(a0 >> 32));
            float lo1 = __uint_as_float((unsigned int)(a1 & 0xffffffffu));
            float hi1 = __uint_as_float((unsigned int)(a1 >> 32));
            float* r_lo = Scur + (size_t)(r0 + 2 * i)     * NHID + nbase + c0;
            float* r_hi = Scur + (size_t)(r0 + 2 * i + 1) * NHID + nbase + c0;
            atomicAdd((float2*)r_lo, make_float2(lo0, lo1));
            atomicAdd((float2*)r_hi, make_float2(hi0, hi1));
        }

        __syncthreads();
        if (tid == 0) {
            asm volatile("red.release.gpu.global.add.u32 [%0], %1;"
                         :: "l"(&g_cnt[(t * NTILE + ntile) * CNT_PAD]), "r"(1u)
                         : "memory");
        }
    }
}

// ---------------------------------------------------------------------------
__global__ void relu_ip(float* __restrict__ p, int n4)
{
    int stride = gridDim.x * blockDim.x;
    for (int i = blockIdx.x * blockDim.x + threadIdx.x; i < n4; i += stride) {
        float4 v = ((float4*)p)[i];
        v.x = fmaxf(v.x, 0.f);
        v.y = fmaxf(v.y, 0.f);
        v.z = fmaxf(v.z, 0.f);
        v.w = fmaxf(v.w, 0.f);
        ((float4*)p)[i] = v;
    }
}

// ---------------------------------------------------------------------------
extern "C" void kernel_launch(void* const* d_in, const int* in_sizes, int n_in,
                              void* d_out, int out_size)
{
    const float* input = (const float*)d_in[0];
    // d_in[1] = length (fixed 512)
    const float* W_in  = (const float*)d_in[2];
    const float* b_in  = (const float*)d_in[3];
    const float* W_ih  = (const float*)d_in[4];
    const float* b_ih  = (const float*)d_in[5];
    const float* W_hh  = (const float*)d_in[6];
    const float* b_hh  = (const float*)d_in[7];
    const float* W_out = (const float*)d_in[8];
    const float* b_out = (const float*)d_in[9];

    float* hid  = (float*)d_out;                 // [T*B, NHID]
    float* outp = hid + (size_t)MROWS * NHID;    // [T*B, NOUT]

    float* Xp = nullptr;
    cudaGetSymbolAddress((void**)&Xp, g_X);

    cudaFuncSetAttribute(rnn_persist,
                         cudaFuncAttributeMaxDynamicSharedMemorySize, SMEM_BYTES);
    cudaFuncSetAttribute(tgemm<true,  false>,
                         cudaFuncAttributeMaxDynamicSharedMemorySize, TG_SMEM);
    cudaFuncSetAttribute(tgemm<false, true>,
                         cudaFuncAttributeMaxDynamicSharedMemorySize, TG_SMEM);
    cudaFuncSetAttribute(tgemm<false, false>,
                         cudaFuncAttributeMaxDynamicSharedMemorySize, TG_SMEM);

    // Phase A: X = relu(IN @ W_in^T + b_in)    [32768x1024], K=256 (tf32 TC)
    tgemm<true, false><<<dim3(NHID / 128, MROWS / 128), 256, TG_SMEM>>>(
        input, W_in, b_in, nullptr, Xp, MROWS, NHID, NIN);

    // Phase B: S = X @ W_ih^T + b_ih + b_hh    [32768x1024], K=1024 (tf32 TC)
    tgemm<false, true><<<dim3(NHID / 128, MROWS / 128), 256, TG_SMEM>>>(
        Xp, W_ih, b_ih, b_hh, hid, MROWS, NHID, NHID);

    // Phase C: persistent recurrence (one launch, fine-grained dependencies)
    epoch_bump<<<1, 1>>>();
    rnn_persist<<<GRID_P, 256, SMEM_BYTES>>>(hid, W_hh);

    // Relu fixup: hiddens = relu(S)
    relu_ip<<<8192, 256>>>(hid, (int)((size_t)MROWS * NHID / 4));

    // Phase D: outputs = H @ W_out^T + b_out   [32768x256], K=1024 (tf32 TC)
    tgemm<false, false><<<dim3(NOUT / 128, MROWS / 128), 256, TG_SMEM>>>(
        hid, W_out, b_out, nullptr, outp, MROWS, NOUT, NHID);
}

// round 10
// speedup vs baseline: 2.3452x; 1.1556x over previous
#include <cuda_runtime.h>
#include <cstdint>

#define T_STEPS 512
#define B_SZ    64
#define NIN     256
#define NHID    1024
#define NOUT    256
#define MROWS   (T_STEPS * B_SZ)   // 32768

#define NTILE   16                 // recurrence n-tiles of 64 cols
#define KSLICE  8                  // recurrence k-slices of 128 k
#define GRID_P  (NTILE * KSLICE)   // 128 persistent blocks

#define CNT_PAD 8

// recurrence smem: 4 tiles (W_hi, W_lo, H_hi, H_lo), each 64 x 128 @ stride 132
#define RS       132
#define RN_TILE  (64 * RS)                 // floats
#define RN_SMEM  (4 * RN_TILE * 4)         // 135168 bytes

// tgemm smem: A,B each [2][128][36] floats
#define TGS    36
#define TG_BUF (128 * TGS)
#define TG_SMEM (4 * TG_BUF * 4)           // 73728 bytes

// 128 MB scratch for X = relu(IN @ W_in^T + b_in)
__device__ float g_X[(size_t)MROWS * NHID];

// fine-grained dependency counters: one per (step, n-tile), monotonic forever
__device__ unsigned int g_cnt[T_STEPS * NTILE * CNT_PAD];
__device__ unsigned long long g_epoch;

__global__ void epoch_bump() { g_epoch += 1ULL; }

// fp32 -> tf32 (round to nearest-even on 10-bit mantissa), kept as fp32 bits
#define TF32R(dst_f, src_f) do {                                      \
    uint32_t _t;                                                      \
    asm("cvt.rna.tf32.f32 %0, %1;" : "=r"(_t) : "f"(src_f));          \
    dst_f = __uint_as_float(_t);                                      \
} while (0)

// tf32 tensor-core mma: D(16x8) += A(16x8) * B(8x8), fp32 accum
#define MMA_TF32(d, a, b)                                                     \
    asm volatile(                                                             \
        "mma.sync.aligned.m16n8k8.row.col.f32.tf32.tf32.f32 "                 \
        "{%0,%1,%2,%3}, {%4,%5,%6,%7}, {%8,%9}, {%0,%1,%2,%3};"               \
        : "+f"((d)[0]), "+f"((d)[1]), "+f"((d)[2]), "+f"((d)[3])              \
        : "r"((a)[0]), "r"((a)[1]), "r"((a)[2]), "r"((a)[3]),                 \
          "r"((b)[0]), "r"((b)[1]))

// ===========================================================================
// tf32 mma.sync GEMM (unchanged from R9 — passing):
//   C[M,N] = act( A[M,K] @ Bw[N,K]^T + bias1 (+ bias2) )
// ===========================================================================
template <bool RELU, bool TWO_BIAS>
__global__ void __launch_bounds__(256)
tgemm(const float* __restrict__ A, const float* __restrict__ Bw,
      const float* __restrict__ bias1, const float* __restrict__ bias2,
      float* __restrict__ C, int M, int N, int K)
{
    extern __shared__ float sm[];
    float* As = sm;
    float* Bs = sm + 2 * TG_BUF;

    const int tid    = threadIdx.x;
    const int lane   = tid & 31;
    const int wid    = tid >> 5;
    const int warp_m = wid & 1;
    const int warp_n = wid >> 1;

    const int bm = blockIdx.y * 128;
    const int bn = blockIdx.x * 128;

    const float* Ag = A  + (size_t)bm * K;
    const float* Bg = Bw + (size_t)bn * K;

    float4 pa[4], pb[4];
#pragma unroll
    for (int i = 0; i < 4; ++i) {
        const int idx = tid + i * 256, row = idx >> 3, kq = (idx & 7) * 4;
        pa[i] = *(const float4*)(Ag + (size_t)row * K + kq);
        pb[i] = *(const float4*)(Bg + (size_t)row * K + kq);
    }
#pragma unroll
    for (int i = 0; i < 4; ++i) {
        const int idx = tid + i * 256, row = idx >> 3, kq = (idx & 7) * 4;
        float* dA = As + row * TGS + kq;
        float* dB = Bs + row * TGS + kq;
        TF32R(dA[0], pa[i].x); TF32R(dA[1], pa[i].y);
        TF32R(dA[2], pa[i].z); TF32R(dA[3], pa[i].w);
        TF32R(dB[0], pb[i].x); TF32R(dB[1], pb[i].y);
        TF32R(dB[2], pb[i].z); TF32R(dB[3], pb[i].w);
    }
    __syncthreads();

    const int aRow = warp_m * 64 + (lane >> 2);
    const int aCol = lane & 3;
    const int bRow = warp_n * 32 + (lane >> 2);
    const int bCol = lane & 3;

    float acc[4][4][4];
#pragma unroll
    for (int fm = 0; fm < 4; ++fm)
#pragma unroll
        for (int fn = 0; fn < 4; ++fn)
#pragma unroll
            for (int q = 0; q < 4; ++q) acc[fm][fn][q] = 0.f;

    int cur = 0;
    for (int k0 = 0; k0 < K; k0 += 32) {
        const bool more = (k0 + 32 < K);
        if (more) {
#pragma unroll
            for (int i = 0; i < 4; ++i) {
                const int idx = tid + i * 256, row = idx >> 3, kq = (idx & 7) * 4;
                pa[i] = *(const float4*)(Ag + (size_t)row * K + k0 + 32 + kq);
                pb[i] = *(const float4*)(Bg + (size_t)row * K + k0 + 32 + kq);
            }
        }

        const float* Ac = As + cur * TG_BUF;
        const float* Bc = Bs + cur * TG_BUF;
#pragma unroll
        for (int k8 = 0; k8 < 4; ++k8) {
            uint32_t af[4][4], bf[4][2];
#pragma unroll
            for (int fm = 0; fm < 4; ++fm) {
                const float* p = Ac + (aRow + fm * 16) * TGS + k8 * 8 + aCol;
                af[fm][0] = __float_as_uint(p[0]);
                af[fm][1] = __float_as_uint(p[8 * TGS]);
                af[fm][2] = __float_as_uint(p[4]);
                af[fm][3] = __float_as_uint(p[8 * TGS + 4]);
            }
#pragma unroll
            for (int fn = 0; fn < 4; ++fn) {
                const float* p = Bc + (bRow + fn * 8) * TGS + k8 * 8 + bCol;
                bf[fn][0] = __float_as_uint(p[0]);
                bf[fn][1] = __float_as_uint(p[4]);
            }
#pragma unroll
            for (int fm = 0; fm < 4; ++fm)
#pragma unroll
                for (int fn = 0; fn < 4; ++fn)
                    MMA_TF32(acc[fm][fn], af[fm], bf[fn]);
        }

        if (more) {
            const int nxt = cur ^ 1;
#pragma unroll
            for (int i = 0; i < 4; ++i) {
                const int idx = tid + i * 256, row = idx >> 3, kq = (idx & 7) * 4;
                float* dA = As + nxt * TG_BUF + row * TGS + kq;
                float* dB = Bs + nxt * TG_BUF + row * TGS + kq;
                TF32R(dA[0], pa[i].x); TF32R(dA[1], pa[i].y);
                TF32R(dA[2], pa[i].z); TF32R(dA[3], pa[i].w);
                TF32R(dB[0], pb[i].x); TF32R(dB[1], pb[i].y);
                TF32R(dB[2], pb[i].z); TF32R(dB[3], pb[i].w);
            }
        }
        __syncthreads();
        cur ^= 1;
    }

#pragma unroll
    for (int fm = 0; fm < 4; ++fm) {
        const int r = bm + warp_m * 64 + fm * 16 + (lane >> 2);
#pragma unroll
        for (int fn = 0; fn < 4; ++fn) {
            const int c = bn + warp_n * 32 + fn * 8 + 2 * (lane & 3);
            float b0 = bias1[c], b1 = bias1[c + 1];
            if (TWO_BIAS) { b0 += bias2[c]; b1 += bias2[c + 1]; }
            float v0 = acc[fm][fn][0] + b0;
            float v1 = acc[fm][fn][1] + b1;
            float v2 = acc[fm][fn][2] + b0;
            float v3 = acc[fm][fn][3] + b1;
            if (RELU) {
                v0 = fmaxf(v0, 0.f); v1 = fmaxf(v1, 0.f);
                v2 = fmaxf(v2, 0.f); v3 = fmaxf(v3, 0.f);
            }
            *(float2*)(C + (size_t)r * N + c)       = make_float2(v0, v1);
            *(float2*)(C + (size_t)(r + 8) * N + c) = make_float2(v2, v3);
        }
    }
}

// ===========================================================================
// Persistent recurrence kernel v4: tensor-core 3xTF32 compensated MMAs.
// Grid = 128 blocks (16 n-tiles x 8 k-slices), 256 threads (8 warps).
// Per block: W_hh tile [64 cols x 128 k] split hi/lo in smem (loaded once);
// per step: stage relu(S[t-1]) slice split hi/lo, compute 64x64 partial via
//   W_hi*h_hi + W_lo*h_hi + W_hi*h_lo   (near-fp32 accuracy, fp32 accum),
// float2 REDs into S[t], fine-grained (step, n-tile) counter publish.
// Warp grid: 4 row-groups (16 rows) x 2 col-halves (32 cols, 4 fn frags).
// ===========================================================================
__global__ void __launch_bounds__(256)
rnn_persist(float* __restrict__ hid, const float* __restrict__ Whh)
{
    extern __shared__ float fsmem[];
    float* Whi = fsmem;                  // [64 cols][RS]
    float* Wlo = fsmem + RN_TILE;
    float* Hhi = fsmem + 2 * RN_TILE;    // [64 rows][RS]
    float* Hlo = fsmem + 3 * RN_TILE;

    const int tid    = threadIdx.x;
    const int lane   = tid & 31;
    const int wid    = tid >> 5;
    const int warp_m = wid & 3;          // 16-row group
    const int warp_n = wid >> 2;         // 32-col half
    const int ntile  = blockIdx.x % NTILE;
    const int nbase  = ntile * 64;
    const int kbase  = (blockIdx.x / NTILE) * 128;
    const int j0     = kbase >> 6;       // first producer n-tile (of 2)

    // ---- load + split W_hh tile once: cols [nbase,nbase+64), k [kbase,+128)
    {
        const int col = tid >> 2;
#pragma unroll
        for (int it = 0; it < 8; ++it) {
            const int k4 = ((tid & 3) + it * 4) * 4;
            float4 w = *(const float4*)(Whh + (size_t)(nbase + col) * NHID + kbase + k4);
            float4 hi, lo;
            TF32R(hi.x, w.x); TF32R(hi.y, w.y); TF32R(hi.z, w.z); TF32R(hi.w, w.w);
            TF32R(lo.x, w.x - hi.x); TF32R(lo.y, w.y - hi.y);
            TF32R(lo.z, w.z - hi.z); TF32R(lo.w, w.w - hi.w);
            *(float4*)(Whi + col * RS + k4) = hi;
            *(float4*)(Wlo + col * RS + k4) = lo;
        }
    }
    __syncthreads();

    const unsigned int target = (unsigned int)(g_epoch * KSLICE);

    // fragment base indices
    const int aRow = warp_m * 16 + (lane >> 2);   // H rows (batch)
    const int aCol = lane & 3;
    const int bCol = lane & 3;

    for (int t = 1; t < T_STEPS; ++t) {
        const float* Sprev = hid + (size_t)(t - 1) * B_SZ * NHID;
        float*       Scur  = hid + (size_t)t * B_SZ * NHID;

        // ---- wait for the 2 producer counters of step t-1 (skip t==1)
        if (t > 1) {
            if (tid == 0 || tid == 32) {
                const int jj = (tid == 0) ? j0 : j0 + 1;
                const unsigned int* cp = &g_cnt[((t - 1) * NTILE + jj) * CNT_PAD];
                unsigned int v;
                do {
                    asm volatile("ld.relaxed.gpu.global.u32 %0, [%1];"
                                 : "=r"(v) : "l"(cp) : "memory");
                } while (v < target);
                asm volatile("ld.acquire.gpu.global.u32 %0, [%1];"
                             : "=r"(v) : "l"(cp) : "memory");
            }
            __syncthreads();
        }

        // ---- stage relu(S[t-1]) slice [64 rows x 128 k], split hi/lo
        {
            const int row = tid >> 2;
#pragma unroll
            for (int it = 0; it < 8; ++it) {
                const int k4 = ((tid & 3) + it * 4) * 4;
                float4 v = __ldcg((const float4*)(Sprev + (size_t)row * NHID + kbase + k4));
                v.x = fmaxf(v.x, 0.f); v.y = fmaxf(v.y, 0.f);
                v.z = fmaxf(v.z, 0.f); v.w = fmaxf(v.w, 0.f);
                float4 hi, lo;
                TF32R(hi.x, v.x); TF32R(hi.y, v.y); TF32R(hi.z, v.z); TF32R(hi.w, v.w);
                TF32R(lo.x, v.x - hi.x); TF32R(lo.y, v.y - hi.y);
                TF32R(lo.z, v.z - hi.z); TF32R(lo.w, v.w - hi.w);
                *(float4*)(Hhi + row * RS + k4) = hi;
                *(float4*)(Hlo + row * RS + k4) = lo;
            }
        }
        __syncthreads();

        // ---- 64x64 partial via compensated tensor MMAs
        float acc[4][4];
#pragma unroll
        for (int fn = 0; fn < 4; ++fn)
#pragma unroll
            for (int q = 0; q < 4; ++q) acc[fn][q] = 0.f;

#pragma unroll 4
        for (int k8 = 0; k8 < 16; ++k8) {
            uint32_t ah[4], al[4];
            {
                const float* p = Hhi + aRow * RS + k8 * 8 + aCol;
                ah[0] = __float_as_uint(p[0]);
                ah[1] = __float_as_uint(p[8 * RS]);
                ah[2] = __float_as_uint(p[4]);
                ah[3] = __float_as_uint(p[8 * RS + 4]);
                const float* q = Hlo + aRow * RS + k8 * 8 + aCol;
                al[0] = __float_as_uint(q[0]);
                al[1] = __float_as_uint(q[8 * RS]);
                al[2] = __float_as_uint(q[4]);
                al[3] = __float_as_uint(q[8 * RS + 4]);
            }
#pragma unroll
            for (int fn = 0; fn < 4; ++fn) {
                const int brow = warp_n * 32 + fn * 8 + (lane >> 2);
                const float* pb = Whi + brow * RS + k8 * 8 + bCol;
                const float* qb = Wlo + brow * RS + k8 * 8 + bCol;
                uint32_t bh[2], bl[2];
                bh[0] = __float_as_uint(pb[0]); bh[1] = __float_as_uint(pb[4]);
                bl[0] = __float_as_uint(qb[0]); bl[1] = __float_as_uint(qb[4]);
                MMA_TF32(acc[fn], ah, bh);   // hi*hi
                MMA_TF32(acc[fn], al, bh);   // lo_h*hi_w
                MMA_TF32(acc[fn], ah, bl);   // hi_h*lo_w
            }
        }

        // ---- combine partials into S[t]: float2 REDs
        {
            const int m = warp_m * 16 + (lane >> 2);
#pragma unroll
            for (int fn = 0; fn < 4; ++fn) {
                const int c = nbase + warp_n * 32 + fn * 8 + 2 * (lane & 3);
                float* p0 = Scur + (size_t)m * NHID + c;
                float* p1 = Scur + (size_t)(m + 8) * NHID + c;
                atomicAdd((float2*)p0, make_float2(acc[fn][0], acc[fn][1]));
                atomicAdd((float2*)p1, make_float2(acc[fn][2], acc[fn][3]));
            }
        }

        // ---- publish this block's n-tile contribution for step t
        __syncthreads();
        if (tid == 0) {
            asm volatile("red.release.gpu.global.add.u32 [%0], %1;"
                         :: "l"(&g_cnt[(t * NTILE + ntile) * CNT_PAD]), "r"(1u)
                         : "memory");
        }
    }
}

// ---------------------------------------------------------------------------
__global__ void relu_ip(float* __restrict__ p, int n4)
{
    int stride = gridDim.x * blockDim.x;
    for (int i = blockIdx.x * blockDim.x + threadIdx.x; i < n4; i += stride) {
        float4 v = ((float4*)p)[i];
        v.x = fmaxf(v.x, 0.f);
        v.y = fmaxf(v.y, 0.f);
        v.z = fmaxf(v.z, 0.f);
        v.w = fmaxf(v.w, 0.f);
        ((float4*)p)[i] = v;
    }
}

// ---------------------------------------------------------------------------
extern "C" void kernel_launch(void* const* d_in, const int* in_sizes, int n_in,
                              void* d_out, int out_size)
{
    const float* input = (const float*)d_in[0];
    // d_in[1] = length (fixed 512)
    const float* W_in  = (const float*)d_in[2];
    const float* b_in  = (const float*)d_in[3];
    const float* W_ih  = (const float*)d_in[4];
    const float* b_ih  = (const float*)d_in[5];
    const float* W_hh  = (const float*)d_in[6];
    const float* b_hh  = (const float*)d_in[7];
    const float* W_out = (const float*)d_in[8];
    const float* b_out = (const float*)d_in[9];

    float* hid  = (float*)d_out;                 // [T*B, NHID]
    float* outp = hid + (size_t)MROWS * NHID;    // [T*B, NOUT]

    float* Xp = nullptr;
    cudaGetSymbolAddress((void**)&Xp, g_X);

    cudaFuncSetAttribute(rnn_persist,
                         cudaFuncAttributeMaxDynamicSharedMemorySize, RN_SMEM);
    cudaFuncSetAttribute(tgemm<true,  false>,
                         cudaFuncAttributeMaxDynamicSharedMemorySize, TG_SMEM);
    cudaFuncSetAttribute(tgemm<false, true>,
                         cudaFuncAttributeMaxDynamicSharedMemorySize, TG_SMEM);
    cudaFuncSetAttribute(tgemm<false, false>,
                         cudaFuncAttributeMaxDynamicSharedMemorySize, TG_SMEM);

    // Phase A: X = relu(IN @ W_in^T + b_in)    [32768x1024], K=256 (tf32 TC)
    tgemm<true, false><<<dim3(NHID / 128, MROWS / 128), 256, TG_SMEM>>>(
        input, W_in, b_in, nullptr, Xp, MROWS, NHID, NIN);

    // Phase B: S = X @ W_ih^T + b_ih + b_hh    [32768x1024], K=1024 (tf32 TC)
    tgemm<false, true><<<dim3(NHID / 128, MROWS / 128), 256, TG_SMEM>>>(
        Xp, W_ih, b_ih, b_hh, hid, MROWS, NHID, NHID);

    // Phase C: persistent recurrence (tensor-core 3xTF32, fine-grained deps)
    epoch_bump<<<1, 1>>>();
    rnn_persist<<<GRID_P, 256, RN_SMEM>>>(hid, W_hh);

    // Relu fixup: hiddens = relu(S)
    relu_ip<<<8192, 256>>>(hid, (int)((size_t)MROWS * NHID / 4));

    // Phase D: outputs = H @ W_out^T + b_out   [32768x256], K=1024 (tf32 TC)
    tgemm<false, false><<<dim3(NOUT / 128, MROWS / 128), 256, TG_SMEM>>>(
        hid, W_out, b_out, nullptr, outp, MROWS, NOUT, NHID);
}

// round 11
// speedup vs baseline: 2.5591x; 1.0912x over previous
#include <cuda_runtime.h>
#include <cstdint>

#define T_STEPS 512
#define B_SZ    64
#define B_HALF  32                 // rows per chain
#define NCHAIN  2                  // independent batch chains
#define NIN     256
#define NHID    1024
#define NOUT    256
#define MROWS   (T_STEPS * B_SZ)   // 32768

#define NTILE   16                 // recurrence n-tiles of 64 cols
#define KSLICE  8                  // recurrence k-slices of 128 k
#define GRID_P  (NCHAIN * NTILE * KSLICE)   // 256 persistent blocks

#define CNT_PAD 8

// recurrence smem: W_hi, W_lo (64 x 128 each) + H fp32 (32 x 128), stride 132
#define RS       132
#define RW_TILE  (64 * RS)
#define RH_TILE  (B_HALF * RS)
#define RN_SMEM  ((2 * RW_TILE + RH_TILE) * 4)   // 84480 bytes

// tgemm smem: A,B each [2][128][36] floats
#define TGS    36
#define TG_BUF (128 * TGS)
#define TG_SMEM (4 * TG_BUF * 4)           // 73728 bytes

// 128 MB scratch for X = relu(IN @ W_in^T + b_in)
__device__ float g_X[(size_t)MROWS * NHID];

// dependency counters: one per (chain, step, n-tile), monotonic forever
__device__ unsigned int g_cnt[NCHAIN * T_STEPS * NTILE * CNT_PAD];
__device__ unsigned long long g_epoch;

__global__ void epoch_bump() { g_epoch += 1ULL; }

// fp32 -> tf32 (round-to-nearest on 10-bit mantissa), kept as fp32 bits
#define TF32R(dst_f, src_f) do {                                      \
    uint32_t _t;                                                      \
    asm("cvt.rna.tf32.f32 %0, %1;" : "=r"(_t) : "f"(src_f));          \
    dst_f = __uint_as_float(_t);                                      \
} while (0)

// same but producing the u32 register directly
#define TF32U(dst_u, src_f) \
    asm("cvt.rna.tf32.f32 %0, %1;" : "=r"(dst_u) : "f"(src_f))

// tf32 tensor-core mma: D(16x8) += A(16x8) * B(8x8), fp32 accum
#define MMA_TF32(d, a, b)                                                     \
    asm volatile(                                                             \
        "mma.sync.aligned.m16n8k8.row.col.f32.tf32.tf32.f32 "                 \
        "{%0,%1,%2,%3}, {%4,%5,%6,%7}, {%8,%9}, {%0,%1,%2,%3};"               \
        : "+f"((d)[0]), "+f"((d)[1]), "+f"((d)[2]), "+f"((d)[3])              \
        : "r"((a)[0]), "r"((a)[1]), "r"((a)[2]), "r"((a)[3]),                 \
          "r"((b)[0]), "r"((b)[1]))

// ===========================================================================
// tf32 mma.sync GEMM (unchanged from R9/R10 — passing):
//   C[M,N] = act( A[M,K] @ Bw[N,K]^T + bias1 (+ bias2) )
// ===========================================================================
template <bool RELU, bool TWO_BIAS>
__global__ void __launch_bounds__(256)
tgemm(const float* __restrict__ A, const float* __restrict__ Bw,
      const float* __restrict__ bias1, const float* __restrict__ bias2,
      float* __restrict__ C, int M, int N, int K)
{
    extern __shared__ float sm[];
    float* As = sm;
    float* Bs = sm + 2 * TG_BUF;

    const int tid    = threadIdx.x;
    const int lane   = tid & 31;
    const int wid    = tid >> 5;
    const int warp_m = wid & 1;
    const int warp_n = wid >> 1;

    const int bm = blockIdx.y * 128;
    const int bn = blockIdx.x * 128;

    const float* Ag = A  + (size_t)bm * K;
    const float* Bg = Bw + (size_t)bn * K;

    float4 pa[4], pb[4];
#pragma unroll
    for (int i = 0; i < 4; ++i) {
        const int idx = tid + i * 256, row = idx >> 3, kq = (idx & 7) * 4;
        pa[i] = *(const float4*)(Ag + (size_t)row * K + kq);
        pb[i] = *(const float4*)(Bg + (size_t)row * K + kq);
    }
#pragma unroll
    for (int i = 0; i < 4; ++i) {
        const int idx = tid + i * 256, row = idx >> 3, kq = (idx & 7) * 4;
        float* dA = As + row * TGS + kq;
        float* dB = Bs + row * TGS + kq;
        TF32R(dA[0], pa[i].x); TF32R(dA[1], pa[i].y);
        TF32R(dA[2], pa[i].z); TF32R(dA[3], pa[i].w);
        TF32R(dB[0], pb[i].x); TF32R(dB[1], pb[i].y);
        TF32R(dB[2], pb[i].z); TF32R(dB[3], pb[i].w);
    }
    __syncthreads();

    const int aRow = warp_m * 64 + (lane >> 2);
    const int aCol = lane & 3;
    const int bRow = warp_n * 32 + (lane >> 2);
    const int bCol = lane & 3;

    float acc[4][4][4];
#pragma unroll
    for (int fm = 0; fm < 4; ++fm)
#pragma unroll
        for (int fn = 0; fn < 4; ++fn)
#pragma unroll
            for (int q = 0; q < 4; ++q) acc[fm][fn][q] = 0.f;

    int cur = 0;
    for (int k0 = 0; k0 < K; k0 += 32) {
        const bool more = (k0 + 32 < K);
        if (more) {
#pragma unroll
            for (int i = 0; i < 4; ++i) {
                const int idx = tid + i * 256, row = idx >> 3, kq = (idx & 7) * 4;
                pa[i] = *(const float4*)(Ag + (size_t)row * K + k0 + 32 + kq);
                pb[i] = *(const float4*)(Bg + (size_t)row * K + k0 + 32 + kq);
            }
        }

        const float* Ac = As + cur * TG_BUF;
        const float* Bc = Bs + cur * TG_BUF;
#pragma unroll
        for (int k8 = 0; k8 < 4; ++k8) {
            uint32_t af[4][4], bf[4][2];
#pragma unroll
            for (int fm = 0; fm < 4; ++fm) {
                const float* p = Ac + (aRow + fm * 16) * TGS + k8 * 8 + aCol;
                af[fm][0] = __float_as_uint(p[0]);
                af[fm][1] = __float_as_uint(p[8 * TGS]);
                af[fm][2] = __float_as_uint(p[4]);
                af[fm][3] = __float_as_uint(p[8 * TGS + 4]);
            }
#pragma unroll
            for (int fn = 0; fn < 4; ++fn) {
                const float* p = Bc + (bRow + fn * 8) * TGS + k8 * 8 + bCol;
                bf[fn][0] = __float_as_uint(p[0]);
                bf[fn][1] = __float_as_uint(p[4]);
            }
#pragma unroll
            for (int fm = 0; fm < 4; ++fm)
#pragma unroll
                for (int fn = 0; fn < 4; ++fn)
                    MMA_TF32(acc[fm][fn], af[fm], bf[fn]);
        }

        if (more) {
            const int nxt = cur ^ 1;
#pragma unroll
            for (int i = 0; i < 4; ++i) {
                const int idx = tid + i * 256, row = idx >> 3, kq = (idx & 7) * 4;
                float* dA = As + nxt * TG_BUF + row * TGS + kq;
                float* dB = Bs + nxt * TG_BUF + row * TGS + kq;
                TF32R(dA[0], pa[i].x); TF32R(dA[1], pa[i].y);
                TF32R(dA[2], pa[i].z); TF32R(dA[3], pa[i].w);
                TF32R(dB[0], pb[i].x); TF32R(dB[1], pb[i].y);
                TF32R(dB[2], pb[i].z); TF32R(dB[3], pb[i].w);
            }
        }
        __syncthreads();
        cur ^= 1;
    }

#pragma unroll
    for (int fm = 0; fm < 4; ++fm) {
        const int r = bm + warp_m * 64 + fm * 16 + (lane >> 2);
#pragma unroll
        for (int fn = 0; fn < 4; ++fn) {
            const int c = bn + warp_n * 32 + fn * 8 + 2 * (lane & 3);
            float b0 = bias1[c], b1 = bias1[c + 1];
            if (TWO_BIAS) { b0 += bias2[c]; b1 += bias2[c + 1]; }
            float v0 = acc[fm][fn][0] + b0;
            float v1 = acc[fm][fn][1] + b1;
            float v2 = acc[fm][fn][2] + b0;
            float v3 = acc[fm][fn][3] + b1;
            if (RELU) {
                v0 = fmaxf(v0, 0.f); v1 = fmaxf(v1, 0.f);
                v2 = fmaxf(v2, 0.f); v3 = fmaxf(v3, 0.f);
            }
            *(float2*)(C + (size_t)r * N + c)       = make_float2(v0, v1);
            *(float2*)(C + (size_t)(r + 8) * N + c) = make_float2(v2, v3);
        }
    }
}

// ===========================================================================
// Persistent recurrence v5: 2 independent batch chains (32 rows each),
// 256 blocks total, 2 blocks/SM, tensor-core 3xTF32 compensated MMAs.
// Per block: W_hh tile [64 cols x 128 k] split hi/lo in smem (loaded once);
// H staged fp32 (no pre-split — hi/lo computed in registers at frag load).
// Warp grid: 2 row-groups (16 rows) x 4 col-groups (16 cols = 2 fn frags).
// ===========================================================================
__global__ void __launch_bounds__(256, 2)
rnn_persist(float* __restrict__ hid, const float* __restrict__ Whh)
{
    extern __shared__ float fsmem[];
    float* Whi = fsmem;                  // [64 cols][RS]
    float* Wlo = fsmem + RW_TILE;
    float* Hs  = fsmem + 2 * RW_TILE;    // [32 rows][RS], fp32

    const int tid    = threadIdx.x;
    const int lane   = tid & 31;
    const int wid    = tid >> 5;
    const int warp_m = wid & 1;          // 16-row group within the 32-row chain
    const int warp_n = wid >> 1;         // 0..3 -> 16-col group (2 fn frags)

    const int bid   = blockIdx.x;
    const int chain = bid >> 7;          // 0 or 1
    const int lb    = bid & 127;
    const int ntile = lb % NTILE;
    const int nbase = ntile * 64;
    const int kbase = (lb / NTILE) * 128;
    const int j0    = kbase >> 6;        // first producer n-tile (of 2)
    const int rbase = chain * B_HALF;    // batch-row base of this chain

    // ---- load + split W_hh tile once: cols [nbase,+64), k [kbase,+128)
    {
        const int col = tid >> 2;
#pragma unroll
        for (int it = 0; it < 8; ++it) {
            const int k4 = ((tid & 3) + it * 4) * 4;
            float4 w = *(const float4*)(Whh + (size_t)(nbase + col) * NHID + kbase + k4);
            float4 hi, lo;
            TF32R(hi.x, w.x); TF32R(hi.y, w.y); TF32R(hi.z, w.z); TF32R(hi.w, w.w);
            TF32R(lo.x, w.x - hi.x); TF32R(lo.y, w.y - hi.y);
            TF32R(lo.z, w.z - hi.z); TF32R(lo.w, w.w - hi.w);
            *(float4*)(Whi + col * RS + k4) = hi;
            *(float4*)(Wlo + col * RS + k4) = lo;
        }
    }
    __syncthreads();

    const unsigned int target = (unsigned int)(g_epoch * KSLICE);

    const int aRow = warp_m * 16 + (lane >> 2);   // H row within chain (0..31 w/ +8)
    const int aCol = lane & 3;
    const int bCol = lane & 3;

    for (int t = 1; t < T_STEPS; ++t) {
        const float* Sprev = hid + (size_t)(t - 1) * B_SZ * NHID;
        float*       Scur  = hid + (size_t)t * B_SZ * NHID;

        // ---- wait for the 2 producer counters of step t-1 (this chain only)
        if (t > 1) {
            if (tid == 0 || tid == 32) {
                const int jj = (tid == 0) ? j0 : j0 + 1;
                const unsigned int* cp =
                    &g_cnt[(((size_t)chain * T_STEPS + (t - 1)) * NTILE + jj) * CNT_PAD];
                unsigned int v;
                do {
                    asm volatile("ld.relaxed.gpu.global.u32 %0, [%1];"
                                 : "=r"(v) : "l"(cp) : "memory");
                } while (v < target);
                asm volatile("ld.acquire.gpu.global.u32 %0, [%1];"
                             : "=r"(v) : "l"(cp) : "memory");
            }
            __syncthreads();
        }

        // ---- stage relu(S[t-1]) slice [32 rows x 128 k] fp32 into Hs
        {
            const int row = tid >> 3;            // 0..31
#pragma unroll
            for (int it = 0; it < 4; ++it) {
                const int c4 = ((tid & 7) + it * 8) * 4;   // float offset 0..124
                float4 v = __ldcg((const float4*)(Sprev +
                            (size_t)(rbase + row) * NHID + kbase + c4));
                v.x = fmaxf(v.x, 0.f); v.y = fmaxf(v.y, 0.f);
                v.z = fmaxf(v.z, 0.f); v.w = fmaxf(v.w, 0.f);
                *(float4*)(Hs + row * RS + c4) = v;
            }
        }
        __syncthreads();

        // ---- 16(x2 row-frag rows)x32 partial via compensated tensor MMAs
        float acc[2][4];
#pragma unroll
        for (int fn = 0; fn < 2; ++fn)
#pragma unroll
            for (int q = 0; q < 4; ++q) acc[fn][q] = 0.f;

#pragma unroll 4
        for (int k8 = 0; k8 < 16; ++k8) {
            // a fragments: load fp32 H, split hi/lo in registers
            const float* p = Hs + aRow * RS + k8 * 8 + aCol;
            float f0 = p[0], f1 = p[8 * RS], f2 = p[4], f3 = p[8 * RS + 4];
            uint32_t ah[4], al[4];
            float h0, h1, h2, h3;
            TF32R(h0, f0); TF32R(h1, f1); TF32R(h2, f2); TF32R(h3, f3);
            ah[0] = __float_as_uint(h0); ah[1] = __float_as_uint(h1);
            ah[2] = __float_as_uint(h2); ah[3] = __float_as_uint(h3);
            TF32U(al[0], f0 - h0); TF32U(al[1], f1 - h1);
            TF32U(al[2], f2 - h2); TF32U(al[3], f3 - h3);
#pragma unroll
            for (int fn = 0; fn < 2; ++fn) {
                const int brow = warp_n * 16 + fn * 8 + (lane >> 2);
                const float* pb = Whi + brow * RS + k8 * 8 + bCol;
                const float* qb = Wlo + brow * RS + k8 * 8 + bCol;
                uint32_t bh[2], bl[2];
                bh[0] = __float_as_uint(pb[0]); bh[1] = __float_as_uint(pb[4]);
                bl[0] = __float_as_uint(qb[0]); bl[1] = __float_as_uint(qb[4]);
                MMA_TF32(acc[fn], ah, bh);   // hi*hi
                MMA_TF32(acc[fn], al, bh);   // lo_h*hi_w
                MMA_TF32(acc[fn], ah, bl);   // hi_h*lo_w
            }
        }

        // ---- combine partials into S[t]: float2 REDs (rows of this chain)
        {
            const int m = rbase + warp_m * 16 + (lane >> 2);
#pragma unroll
            for (int fn = 0; fn < 2; ++fn) {
                const int c = nbase + warp_n * 16 + fn * 8 + 2 * (lane & 3);
                float* p0 = Scur + (size_t)m * NHID + c;
                float* p1 = Scur + (size_t)(m + 8) * NHID + c;
                atomicAdd((float2*)p0, make_float2(acc[fn][0], acc[fn][1]));
                atomicAdd((float2*)p1, make_float2(acc[fn][2], acc[fn][3]));
            }
        }

        // ---- publish this block's n-tile contribution for step t
        __syncthreads();
        if (tid == 0) {
            asm volatile("red.release.gpu.global.add.u32 [%0], %1;"
                         :: "l"(&g_cnt[(((size_t)chain * T_STEPS + t) * NTILE
                                        + ntile) * CNT_PAD]), "r"(1u)
                         : "memory");
        }
    }
}

// ---------------------------------------------------------------------------
__global__ void relu_ip(float* __restrict__ p, int n4)
{
    int stride = gridDim.x * blockDim.x;
    for (int i = blockIdx.x * blockDim.x + threadIdx.x; i < n4; i += stride) {
        float4 v = ((float4*)p)[i];
        v.x = fmaxf(v.x, 0.f);
        v.y = fmaxf(v.y, 0.f);
        v.z = fmaxf(v.z, 0.f);
        v.w = fmaxf(v.w, 0.f);
        ((float4*)p)[i] = v;
    }
}

// ---------------------------------------------------------------------------
extern "C" void kernel_launch(void* const* d_in, const int* in_sizes, int n_in,
                              void* d_out, int out_size)
{
    const float* input = (const float*)d_in[0];
    // d_in[1] = length (fixed 512)
    const float* W_in  = (const float*)d_in[2];
    const float* b_in  = (const float*)d_in[3];
    const float* W_ih  = (const float*)d_in[4];
    const float* b_ih  = (const float*)d_in[5];
    const float* W_hh  = (const float*)d_in[6];
    const float* b_hh  = (const float*)d_in[7];
    const float* W_out = (const float*)d_in[8];
    const float* b_out = (const float*)d_in[9];

    float* hid  = (float*)d_out;                 // [T*B, NHID]
    float* outp = hid + (size_t)MROWS * NHID;    // [T*B, NOUT]

    float* Xp = nullptr;
    cudaGetSymbolAddress((void**)&Xp, g_X);

    cudaFuncSetAttribute(rnn_persist,
                         cudaFuncAttributeMaxDynamicSharedMemorySize, RN_SMEM);
    cudaFuncSetAttribute(tgemm<true,  false>,
                         cudaFuncAttributeMaxDynamicSharedMemorySize, TG_SMEM);
    cudaFuncSetAttribute(tgemm<false, true>,
                         cudaFuncAttributeMaxDynamicSharedMemorySize, TG_SMEM);
    cudaFuncSetAttribute(tgemm<false, false>,
                         cudaFuncAttributeMaxDynamicSharedMemorySize, TG_SMEM);

    // Phase A: X = relu(IN @ W_in^T + b_in)    [32768x1024], K=256 (tf32 TC)
    tgemm<true, false><<<dim3(NHID / 128, MROWS / 128), 256, TG_SMEM>>>(
        input, W_in, b_in, nullptr, Xp, MROWS, NHID, NIN);

    // Phase B: S = X @ W_ih^T + b_ih + b_hh    [32768x1024], K=1024 (tf32 TC)
    tgemm<false, true><<<dim3(NHID / 128, MROWS / 128), 256, TG_SMEM>>>(
        Xp, W_ih, b_ih, b_hh, hid, MROWS, NHID, NHID);

    // Phase C: persistent recurrence — 2 independent batch chains, 256 blocks
    epoch_bump<<<1, 1>>>();
    rnn_persist<<<GRID_P, 256, RN_SMEM>>>(hid, W_hh);

    // Relu fixup: hiddens = relu(S)
    relu_ip<<<8192, 256>>>(hid, (int)((size_t)MROWS * NHID / 4));

    // Phase D: outputs = H @ W_out^T + b_out   [32768x256], K=1024 (tf32 TC)
    tgemm<false, false><<<dim3(NOUT / 128, MROWS / 128), 256, TG_SMEM>>>(
        hid, W_out, b_out, nullptr, outp, MROWS, NOUT, NHID);
}